// round 15
// baseline (speedup 1.0000x reference)
#include <cuda_runtime.h>
#include <cuda_bf16.h>
#include <cuda_fp16.h>
#include <stdint.h>
#include <math.h>

// ---------------- static config ----------------
#define B_    4
#define BC_   256
#define PC_   64
#define HC_   256
#define H_    200
#define W_    400
#define P_    10
#define Hg_   20
#define Wg_   40
#define LQ_   800
#define MT_   (B_*LQ_)     // 3200 rows
#define NH_   8
#define NP_   8
#define DH_   32
#define MLPD_ 1024
#define NEXP_ 25600
#define KBEV_ 25600
#define KPR_  6400
#define NOA_  192

// ---------------- scratch ----------------
__device__ float g_tgt [MT_*HC_];
__device__ float g_pr  [MT_*HC_];
__device__ float g_t   [MT_*HC_];
__device__ float g_s   [MT_*HC_];
__device__ float g_val [MT_*HC_];
__device__ float g_attn[MT_*HC_];
__device__ float g_oa  [MT_*NOA_];
__device__ float g_mlp [MT_*MLPD_];
__device__ float g_part [4*MT_*HC_];
__device__ float g_part2[4*MT_*HC_];
__device__ float g_oab [2*NOA_];
__device__ __half g_exph[(size_t)MT_*NEXP_];

// fp16 planes
__device__ __align__(256) __half g_imb [(size_t)MT_*KBEV_];
__device__ __align__(256) __half g_imp [(size_t)MT_*KPR_];
__device__ __align__(256) __half g_wb  [HC_*KBEV_];
__device__ __align__(256) __half g_wp  [HC_*KPR_];
__device__ __align__(256) __half g_we  [NEXP_*HC_];
__device__ __align__(256) __half g_tg16[MT_*HC_];
__device__ __align__(256) __half g_t16 [MT_*HC_];
__device__ __align__(256) __half g_fc116[2*MLPD_*HC_];
__device__ __align__(256) __half g_fc216[2*HC_*MLPD_];
__device__ __align__(256) __half g_vp16 [2*HC_*HC_];
__device__ __align__(256) __half g_op16 [2*HC_*HC_];
__device__ __align__(256) __half g_oaw16[2*NOA_*HC_];

// ---------------- helpers ----------------
__device__ __forceinline__ float gelu_exact(float x) {
    return 0.5f * x * (1.0f + erff(x * 0.70710678118654752f));
}
__device__ __forceinline__ unsigned h2u(__half2 h) {
    return *reinterpret_cast<unsigned*>(&h);
}
__device__ __forceinline__ void mma_f16(float* c,
                                        unsigned a0, unsigned a1, unsigned a2, unsigned a3,
                                        unsigned b0, unsigned b1) {
    asm volatile(
        "mma.sync.aligned.m16n8k16.row.col.f32.f16.f16.f32 "
        "{%0,%1,%2,%3}, {%4,%5,%6,%7}, {%8,%9}, {%0,%1,%2,%3};\n"
        : "+f"(c[0]), "+f"(c[1]), "+f"(c[2]), "+f"(c[3])
        : "r"(a0), "r"(a1), "r"(a2), "r"(a3), "r"(b0), "r"(b1));
}
__device__ __forceinline__ unsigned smem_u32(const void* p) {
    return (unsigned)__cvta_generic_to_shared(p);
}
__device__ __forceinline__ void cp16(unsigned s, const void* g) {
    asm volatile("cp.async.cg.shared.global [%0], [%1], 16;" :: "r"(s), "l"(g));
}
__device__ __forceinline__ void cp_commit() { asm volatile("cp.async.commit_group;"); }
template<int NN> __device__ __forceinline__ void cp_wait() {
    asm volatile("cp.async.wait_group %0;" :: "n"(NN));
}
__device__ __forceinline__ void ldsm4(unsigned &r0, unsigned &r1, unsigned &r2, unsigned &r3,
                                      unsigned addr) {
    asm volatile("ldmatrix.sync.aligned.m8n8.x4.shared.b16 {%0,%1,%2,%3}, [%4];"
                 : "=r"(r0), "=r"(r1), "=r"(r2), "=r"(r3) : "r"(addr));
}

// ==========================================================================
// converts
// ==========================================================================
__global__ void convert_h_k(const float* __restrict__ X,
                            __half* __restrict__ Ph, int n4) {
    for (int i = blockIdx.x * blockDim.x + threadIdx.x; i < n4; i += gridDim.x * blockDim.x) {
        float4 v = ((const float4*)X)[i];
        ((__half2*)Ph)[i * 2]     = __floats2half2_rn(v.x, v.y);
        ((__half2*)Ph)[i * 2 + 1] = __floats2half2_rn(v.z, v.w);
    }
}

__global__ void concat_ow_h_k(const float* __restrict__ off_w, const float* __restrict__ off_b,
                              const float* __restrict__ aw_w,  const float* __restrict__ aw_b,
                              __half* __restrict__ Wc, float* __restrict__ Bc) {
    int n = blockIdx.x, l = blockIdx.y, c = threadIdx.x;
    const float* src = (n < 128) ? off_w + (size_t)(l * 128 + n) * HC_
                                 : aw_w  + (size_t)(l * 64 + (n - 128)) * HC_;
    Wc[(size_t)(l * NOA_ + n) * HC_ + c] = __float2half_rn(src[c]);
    if (c == 0)
        Bc[l * NOA_ + n] = (n < 128) ? off_b[l * 128 + n] : aw_b[l * 64 + n - 128];
}

// ==========================================================================
// im2col -> fp16 plane
// ==========================================================================
template<int CIN>
__global__ void im2col_h_k(const float* __restrict__ X,
                           __half* __restrict__ Ph) {
    __shared__ float s[4000];
    int hg = blockIdx.x, ci = blockIdx.y, b = blockIdx.z;
    int tid = threadIdx.x;
    const int K = CIN * 100;
    const float* src = X + ((size_t)(b * CIN + ci) * H_ + hg * P_) * W_;
    for (int i = tid; i < 4000; i += 256) s[i] = src[i];
    __syncthreads();
    size_t rowbase = (size_t)(b * LQ_ + hg * Wg_);
    for (int j = tid; j < 4000; j += 256) {
        int wg = j / 100, idx = j - wg * 100;
        int py = idx / 10, px = idx - py * 10;
        Ph[(rowbase + wg) * K + ci * 100 + idx] = __float2half_rn(s[py * 400 + wg * 10 + px]);
    }
}

// ==========================================================================
// fp16 mma.sync fast GEMM, 128x128x32, 3-stage cp.async pipeline
// ==========================================================================
#define FB_BIAS 1u
#define FB_GELU 2u
#define FB_F32  4u
#define FB_HALF 8u
#define HSTG 20480
#define NSTG 3

template<unsigned MODE, int SPLIT>
__global__ void __launch_bounds__(256) gfh_k(
        const __half* __restrict__ A_g, const __half* __restrict__ B_g,
        const float* __restrict__ bias, float* __restrict__ C, __half* __restrict__ Ch,
        int N, int K, int y_off) {
    extern __shared__ char smraw[];
    unsigned sbase = smem_u32(smraw);

    int tid = threadIdx.x, warp = tid >> 5, lane = tid & 31;
    int m0 = (blockIdx.y + y_off) * 128, n0 = blockIdx.x * 128;
    int Kc = K / SPLIT;
    int kstart = (SPLIT > 1) ? blockIdx.z * Kc : 0;
    int nk = Kc / 32;
    int wm = (warp >> 2) * 64, wn = (warp & 3) * 32;
    int gid = lane >> 2, tig = lane & 3;

    float acc[4][4][4];
#pragma unroll
    for (int mi = 0; mi < 4; mi++)
#pragma unroll
        for (int ni = 0; ni < 4; ni++)
#pragma unroll
            for (int q = 0; q < 4; q++) acc[mi][ni][q] = 0.f;

    auto load_tile = [&](int kt, int st) {
        int kb = kstart + kt * 32;
        unsigned sb = sbase + st * HSTG;
#pragma unroll
        for (int j = 0; j < 2; j++) {
            int c = j * 256 + tid;
            int row = c >> 2, q = c & 3;
            unsigned so = row * 80 + q * 16;
            cp16(sb +         so, A_g + (size_t)(m0 + row) * K + kb + q * 8);
            cp16(sb + 10240 + so, B_g + (size_t)(n0 + row) * K + kb + q * 8);
        }
    };

    auto compute = [&](int st) {
        unsigned sb = sbase + st * HSTG;
#pragma unroll
        for (int s = 0; s < 2; s++) {
            unsigned ah[4][4], bh[4][2];
            int arow = wm + (lane & 15);
            unsigned abyte = ((lane >> 4) * 16) + s * 32;
#pragma unroll
            for (int mi = 0; mi < 4; mi++) {
                unsigned ad = sb + (arow + mi * 16) * 80 + abyte;
                ldsm4(ah[mi][0], ah[mi][1], ah[mi][2], ah[mi][3], ad);
            }
            int q = lane >> 3, r = lane & 7;
            int brow = wn + ((q >> 1) << 3) + r;
            unsigned bbyte = (q & 1) * 16 + s * 32;
#pragma unroll
            for (int nj = 0; nj < 2; nj++) {
                unsigned bd = sb + 10240 + (brow + nj * 16) * 80 + bbyte;
                unsigned r0, r1, r2, r3;
                ldsm4(r0, r1, r2, r3, bd);
                bh[nj*2][0] = r0; bh[nj*2][1] = r1; bh[nj*2+1][0] = r2; bh[nj*2+1][1] = r3;
            }
#pragma unroll
            for (int mi = 0; mi < 4; mi++)
#pragma unroll
                for (int ni = 0; ni < 4; ni++)
                    mma_f16(acc[mi][ni], ah[mi][0], ah[mi][1], ah[mi][2], ah[mi][3],
                            bh[ni][0], bh[ni][1]);
        }
    };

    // 3-stage pipeline: prefetch depth 2
    load_tile(0, 0);
    cp_commit();
    if (nk > 1) { load_tile(1, 1); cp_commit(); }
    for (int kt = 0; kt < nk; kt++) {
        if (kt + 2 < nk) {
            load_tile(kt + 2, (kt + 2) % NSTG);
            cp_commit();
            cp_wait<2>();
        } else if (kt + 1 < nk) {
            cp_wait<1>();
        } else {
            cp_wait<0>();
        }
        __syncthreads();
        compute(kt % NSTG);
        __syncthreads();
    }

#pragma unroll
    for (int mi = 0; mi < 4; mi++) {
#pragma unroll
        for (int ni = 0; ni < 4; ni++) {
            int m = m0 + wm + mi * 16 + gid;
            int n = n0 + wn + ni * 8 + tig * 2;
            float v0 = acc[mi][ni][0], v1 = acc[mi][ni][1];
            float v2 = acc[mi][ni][2], v3 = acc[mi][ni][3];
            if (SPLIT > 1) {
                float* Cp = C + (size_t)blockIdx.z * ((size_t)MT_ * N);
                Cp[(size_t)m * N + n] = v0;       Cp[(size_t)m * N + n + 1] = v1;
                Cp[(size_t)(m + 8) * N + n] = v2; Cp[(size_t)(m + 8) * N + n + 1] = v3;
            } else {
                if (MODE & FB_BIAS) {
                    float b0 = bias[n], b1 = bias[n + 1];
                    v0 += b0; v1 += b1; v2 += b0; v3 += b1;
                }
                if (MODE & FB_GELU) {
                    v0 = gelu_exact(v0); v1 = gelu_exact(v1);
                    v2 = gelu_exact(v2); v3 = gelu_exact(v3);
                }
                size_t o0 = (size_t)m * N + n, o1 = (size_t)(m + 8) * N + n;
                if (MODE & FB_F32) {
                    C[o0] = v0; C[o0 + 1] = v1; C[o1] = v2; C[o1 + 1] = v3;
                }
                if (MODE & FB_HALF) {
                    Ch[o0] = __float2half(v0); Ch[o0 + 1] = __float2half(v1);
                    Ch[o1] = __float2half(v2); Ch[o1 + 1] = __float2half(v3);
                }
            }
        }
    }
}

// ==========================================================================
// Slow-path fp16 NT GEMM: A fp32 inline->fp16, B pre-fp16. 64x64, 128 thr.
// WRITE_H: also emit fp16 copy of result (for final tgt -> expand input).
// ==========================================================================
#define SSTR 20
template<int HAS_RES, int WRITE_H>
__global__ __launch_bounds__(128) void mma_gemm_h_k(
        const float* __restrict__ A, const __half* __restrict__ B_g,
        const float* __restrict__ bias, const float* __restrict__ R,
        float* __restrict__ C, __half* __restrict__ Ch, int N, int K) {
    __shared__ unsigned Ah[64*SSTR], Bh[64*SSTR];
    int tid  = threadIdx.x;
    int warp = tid >> 5, lane = tid & 31;
    int gid  = lane >> 2, tig = lane & 3;
    int m0 = blockIdx.y * 64, n0 = blockIdx.x * 64;
    int wm = (warp & 1) * 32, wn = (warp >> 1) * 32;

    int row = tid >> 1, half = tid & 1;
    const float* ap = A + (size_t)(m0 + row) * K + half * 16;
    const __half* bp = B_g + (size_t)(n0 + row) * K + half * 16;

    float4 fa[4];
    uint4 fb[2];
#pragma unroll
    for (int i = 0; i < 4; i++) fa[i] = *(const float4*)(ap + i * 4);
#pragma unroll
    for (int i = 0; i < 2; i++) fb[i] = *(const uint4*)(bp + i * 8);

    float acc[2][4][4];
#pragma unroll
    for (int mi = 0; mi < 2; mi++)
#pragma unroll
        for (int ni = 0; ni < 4; ni++)
#pragma unroll
            for (int q = 0; q < 4; q++) acc[mi][ni][q] = 0.f;

    for (int k0 = 0; k0 < K; k0 += 32) {
        int sb = row * SSTR + half * 8;
#pragma unroll
        for (int i = 0; i < 4; i++) {
            Ah[sb + i*2]     = h2u(__floats2half2_rn(fa[i].x, fa[i].y));
            Ah[sb + i*2 + 1] = h2u(__floats2half2_rn(fa[i].z, fa[i].w));
        }
        Bh[sb + 0] = fb[0].x; Bh[sb + 1] = fb[0].y;
        Bh[sb + 2] = fb[0].z; Bh[sb + 3] = fb[0].w;
        Bh[sb + 4] = fb[1].x; Bh[sb + 5] = fb[1].y;
        Bh[sb + 6] = fb[1].z; Bh[sb + 7] = fb[1].w;
        __syncthreads();
        if (k0 + 32 < K) {
#pragma unroll
            for (int i = 0; i < 4; i++) fa[i] = *(const float4*)(ap + k0 + 32 + i * 4);
#pragma unroll
            for (int i = 0; i < 2; i++) fb[i] = *(const uint4*)(bp + k0 + 32 + i * 8);
        }
#pragma unroll
        for (int s = 0; s < 2; s++) {
            unsigned ah[2][4], bh[4][2];
            int p = s * 8 + tig;
#pragma unroll
            for (int mi = 0; mi < 2; mi++) {
                int r0 = (wm + mi * 16 + gid) * SSTR;
                int r8 = r0 + 8 * SSTR;
                ah[mi][0] = Ah[r0 + p];     ah[mi][1] = Ah[r8 + p];
                ah[mi][2] = Ah[r0 + p + 4]; ah[mi][3] = Ah[r8 + p + 4];
            }
#pragma unroll
            for (int ni = 0; ni < 4; ni++) {
                int nr = (wn + ni * 8 + gid) * SSTR;
                bh[ni][0] = Bh[nr + p]; bh[ni][1] = Bh[nr + p + 4];
            }
#pragma unroll
            for (int mi = 0; mi < 2; mi++)
#pragma unroll
                for (int ni = 0; ni < 4; ni++)
                    mma_f16(acc[mi][ni], ah[mi][0], ah[mi][1], ah[mi][2], ah[mi][3],
                            bh[ni][0], bh[ni][1]);
        }
        __syncthreads();
    }
#pragma unroll
    for (int mi = 0; mi < 2; mi++) {
#pragma unroll
        for (int ni = 0; ni < 4; ni++) {
            int m = m0 + wm + mi * 16 + gid;
            int n = n0 + wn + ni * 8 + tig * 2;
            float b0v = bias[n], b1v = bias[n + 1];
            float v0 = acc[mi][ni][0] + b0v, v1 = acc[mi][ni][1] + b1v;
            float v2 = acc[mi][ni][2] + b0v, v3 = acc[mi][ni][3] + b1v;
            if (HAS_RES) {
                const float* rp = R + (size_t)m * N + n;
                v0 += rp[0]; v1 += rp[1];
                v2 += rp[(size_t)8 * N]; v3 += rp[(size_t)8 * N + 1];
            }
            float* cp = C + (size_t)m * N + n;
            cp[0] = v0; cp[1] = v1;
            cp[(size_t)8 * N] = v2; cp[(size_t)8 * N + 1] = v3;
            if (WRITE_H) {
                __half* hp = Ch + (size_t)m * N + n;
                hp[0] = __float2half_rn(v0); hp[1] = __float2half_rn(v1);
                hp[(size_t)8 * N] = __float2half_rn(v2);
                hp[(size_t)8 * N + 1] = __float2half_rn(v3);
            }
        }
    }
}

// ==========================================================================
// Expand scatter (fp16 temp -> fp32 out, + bev residual), z_off for split
// ==========================================================================
__global__ void expand_scatter_k(const __half* __restrict__ T,
                                 const float* __restrict__ bev,
                                 float* __restrict__ out, int z_off) {
    __shared__ float s[400][17];
    int bcg = blockIdx.x, py = blockIdx.y, bz = blockIdx.z + z_off;
    int b = bz / 20, hg = bz % 20;
    int tid = threadIdx.x;
    int mbase = b * LQ_ + hg * Wg_;
    const __half* tb = T + (size_t)mbase * NEXP_ + py * 2560 + bcg * 16;

#pragma unroll
    for (int it = 0; it < 25; it++) {
        int j = it * 256 + tid;
        int unit = j >> 4, bcl = j & 15;
        int wg = unit / 10, px = unit - wg * 10;
        s[unit][bcl] = __half2float(tb[(size_t)wg * NEXP_ + px * 256 + bcl]);
    }
    __syncthreads();

    int rowbase = hg * P_ + py;
#pragma unroll
    for (int it = 0; it < 25; it++) {
        int j = it * 256 + tid;
        int bcl = j / 400, pix = j - bcl * 400;
        int ch = bcg * 16 + bcl;
        size_t gi = (((size_t)b * BC_ + ch) * H_ + rowbase) * W_ + pix;
        out[gi] = s[pix][bcl] + bev[gi];
    }
}

// ==========================================================================
// LayerNorm family
// ==========================================================================
__device__ __forceinline__ float block_ln_val(float x, const float* __restrict__ g,
                                              const float* __restrict__ bt, int c) {
    __shared__ float red[2][8];
    float s = x, sq = x * x;
#pragma unroll
    for (int o = 16; o > 0; o >>= 1) {
        s  += __shfl_down_sync(0xffffffffu, s, o);
        sq += __shfl_down_sync(0xffffffffu, sq, o);
    }
    int w = c >> 5, lane = c & 31;
    if (lane == 0) { red[0][w] = s; red[1][w] = sq; }
    __syncthreads();
    float ts = 0.f, tq = 0.f;
#pragma unroll
    for (int i = 0; i < 8; i++) { ts += red[0][i]; tq += red[1][i]; }
    float mean = ts * (1.0f / HC_);
    float var  = tq * (1.0f / HC_) - mean * mean;
    float inv  = rsqrtf(var + 1e-5f);
    return (x - mean) * inv * g[c] + bt[c];
}

template<int SPLIT>
__global__ void add_pos_ln_red_k(const float* __restrict__ part,
                                 const float* __restrict__ cb,
                                 const float* __restrict__ pos,
                                 const float* __restrict__ g,
                                 const float* __restrict__ bt,
                                 float* __restrict__ Y) {
    int row = blockIdx.x, c = threadIdx.x;
    float x = 0.f;
#pragma unroll
    for (int z = 0; z < SPLIT; z++) x += part[(size_t)z * MT_ * HC_ + (size_t)row * HC_ + c];
    x += cb[c] + pos[(row % LQ_) * HC_ + c];
    Y[(size_t)row * HC_ + c] = block_ln_val(x, g, bt, c);
}

__global__ void ln2_k(const float* __restrict__ X0, float* __restrict__ Y0,
                      const float* __restrict__ X1, float* __restrict__ Y1,
                      const float* __restrict__ g, const float* __restrict__ bt) {
    int row = blockIdx.x, c = threadIdx.x;
    const float* X = blockIdx.y ? X1 : X0;
    float* Y = blockIdx.y ? Y1 : Y0;
    float x = X[(size_t)row * HC_ + c];
    Y[(size_t)row * HC_ + c] = block_ln_val(x, g, bt, c);
}

__global__ void ln_h_k(const float* __restrict__ X,
                       const float* __restrict__ g,
                       const float* __restrict__ bt,
                       __half* __restrict__ Y) {
    int row = blockIdx.x, c = threadIdx.x;
    float x = X[(size_t)row * HC_ + c];
    Y[(size_t)row * HC_ + c] = __float2half_rn(block_ln_val(x, g, bt, c));
}

// ==========================================================================
// Deformable attention
// ==========================================================================
__global__ void deform_k(const float* __restrict__ val,
                         const float* __restrict__ oa,
                         float* __restrict__ attn) {
    int row  = blockIdx.x;
    int h    = threadIdx.x >> 5;
    int lane = threadIdx.x & 31;
    int b = row / LQ_, l = row % LQ_;
    int hg = l / Wg_, wg = l % Wg_;

    float refx = ((float)wg + 0.5f) / (float)Wg_;
    float refy = ((float)hg + 0.5f) / (float)Hg_;

    const float* oarow = oa + (size_t)row * NOA_;
    float lg[NP_];
    float mx = -1e30f;
#pragma unroll
    for (int p = 0; p < NP_; p++) {
        lg[p] = oarow[128 + h * NP_ + p];
        mx = fmaxf(mx, lg[p]);
    }
    float den = 0.f;
#pragma unroll
    for (int p = 0; p < NP_; p++) { lg[p] = expf(lg[p] - mx); den += lg[p]; }
    float invden = 1.0f / den;

    const float* vb = val + (size_t)b * LQ_ * HC_ + h * DH_ + lane;
    float acc = 0.f;

#pragma unroll
    for (int p = 0; p < NP_; p++) {
        float ox = oarow[(h * NP_ + p) * 2 + 0];
        float oy = oarow[(h * NP_ + p) * 2 + 1];
        float x = (refx + ox * (1.0f / Wg_)) * (float)Wg_ - 0.5f;
        float y = (refy + oy * (1.0f / Hg_)) * (float)Hg_ - 0.5f;
        float xf = floorf(x), yf = floorf(y);
        int x0 = (int)xf, y0 = (int)yf;
        float lx = x - xf, ly = y - yf;
        float wp = lg[p] * invden;

        float w00 = (1.f - lx) * (1.f - ly);
        float w10 = lx * (1.f - ly);
        float w01 = (1.f - lx) * ly;
        float w11 = lx * ly;

        if (x0     >= 0 && x0     < Wg_ && y0     >= 0 && y0     < Hg_)
            acc = fmaf(wp * w00, vb[(size_t)(y0 * Wg_ + x0) * HC_], acc);
        if (x0 + 1 >= 0 && x0 + 1 < Wg_ && y0     >= 0 && y0     < Hg_)
            acc = fmaf(wp * w10, vb[(size_t)(y0 * Wg_ + x0 + 1) * HC_], acc);
        if (x0     >= 0 && x0     < Wg_ && y0 + 1 >= 0 && y0 + 1 < Hg_)
            acc = fmaf(wp * w01, vb[(size_t)((y0 + 1) * Wg_ + x0) * HC_], acc);
        if (x0 + 1 >= 0 && x0 + 1 < Wg_ && y0 + 1 >= 0 && y0 + 1 < Hg_)
            acc = fmaf(wp * w11, vb[(size_t)((y0 + 1) * Wg_ + x0 + 1) * HC_], acc);
    }
    attn[(size_t)row * HC_ + h * DH_ + lane] = acc;
}

// ==========================================================================
// host launch
// ==========================================================================
extern "C" void kernel_launch(void* const* d_in, const int* in_sizes, int n_in,
                              void* d_out, int out_size) {
    const float* bev      = (const float*)d_in[0];
    const float* prior    = (const float*)d_in[1];
    const float* pe_bev_w = (const float*)d_in[2];
    const float* pe_bev_b = (const float*)d_in[3];
    const float* pe_pr_w  = (const float*)d_in[4];
    const float* pe_pr_b  = (const float*)d_in[5];
    const float* pos_bev  = (const float*)d_in[6];
    const float* pos_pr   = (const float*)d_in[7];
    const float* ln_bev_g = (const float*)d_in[8];
    const float* ln_bev_b = (const float*)d_in[9];
    const float* ln_pr_g  = (const float*)d_in[10];
    const float* ln_pr_b  = (const float*)d_in[11];
    const float* n1_g     = (const float*)d_in[12];
    const float* n1_b     = (const float*)d_in[13];
    const float* n2_g     = (const float*)d_in[14];
    const float* n2_b     = (const float*)d_in[15];
    const float* off_w    = (const float*)d_in[16];
    const float* off_b    = (const float*)d_in[17];
    const float* aw_w     = (const float*)d_in[18];
    const float* aw_b     = (const float*)d_in[19];
    const float* vp_w     = (const float*)d_in[20];
    const float* vp_b     = (const float*)d_in[21];
    const float* op_w     = (const float*)d_in[22];
    const float* op_b     = (const float*)d_in[23];
    const float* fc1_w    = (const float*)d_in[24];
    const float* fc1_b    = (const float*)d_in[25];
    const float* fc2_w    = (const float*)d_in[26];
    const float* fc2_b    = (const float*)d_in[27];
    const float* expand_w = (const float*)d_in[28];
    float* out = (float*)d_out;

    float *tgt, *pr, *t, *s, *val, *attn, *oa, *mlp, *part, *part2, *oab;
    __half *exph, *imb, *imp, *wb, *wp, *we, *tg16, *t16;
    __half *fc116, *fc216, *vp16, *op16, *oaw16;
    cudaGetSymbolAddress((void**)&tgt,  g_tgt);
    cudaGetSymbolAddress((void**)&pr,   g_pr);
    cudaGetSymbolAddress((void**)&t,    g_t);
    cudaGetSymbolAddress((void**)&s,    g_s);
    cudaGetSymbolAddress((void**)&val,  g_val);
    cudaGetSymbolAddress((void**)&attn, g_attn);
    cudaGetSymbolAddress((void**)&oa,   g_oa);
    cudaGetSymbolAddress((void**)&mlp,  g_mlp);
    cudaGetSymbolAddress((void**)&part, g_part);
    cudaGetSymbolAddress((void**)&part2,g_part2);
    cudaGetSymbolAddress((void**)&oab,  g_oab);
    cudaGetSymbolAddress((void**)&exph, g_exph);
    cudaGetSymbolAddress((void**)&imb,  g_imb);
    cudaGetSymbolAddress((void**)&imp,  g_imp);
    cudaGetSymbolAddress((void**)&wb,   g_wb);
    cudaGetSymbolAddress((void**)&wp,   g_wp);
    cudaGetSymbolAddress((void**)&we,   g_we);
    cudaGetSymbolAddress((void**)&tg16, g_tg16);
    cudaGetSymbolAddress((void**)&t16,  g_t16);
    cudaGetSymbolAddress((void**)&fc116,g_fc116);
    cudaGetSymbolAddress((void**)&fc216,g_fc216);
    cudaGetSymbolAddress((void**)&vp16, g_vp16);
    cudaGetSymbolAddress((void**)&op16, g_op16);
    cudaGetSymbolAddress((void**)&oaw16,g_oaw16);

    cudaFuncSetAttribute(gfh_k<0u,4>, cudaFuncAttributeMaxDynamicSharedMemorySize, NSTG*HSTG);
    cudaFuncSetAttribute(gfh_k<FB_HALF,1>, cudaFuncAttributeMaxDynamicSharedMemorySize, NSTG*HSTG);
    cudaFuncSetAttribute(gfh_k<FB_BIAS|FB_GELU|FB_F32,1>, cudaFuncAttributeMaxDynamicSharedMemorySize, NSTG*HSTG);

    static cudaStream_t s1 = nullptr, s2 = nullptr;
    static cudaEvent_t ev[16];
    if (!s1) {
        cudaStreamCreateWithFlags(&s1, cudaStreamNonBlocking);
        cudaStreamCreateWithFlags(&s2, cudaStreamNonBlocking);
        for (int i = 0; i < 16; i++) cudaEventCreateWithFlags(&ev[i], cudaEventDisableTiming);
    }

    // ---- fork ----
    cudaEventRecord(ev[0], 0);
    cudaStreamWaitEvent(s1, ev[0], 0);
    cudaStreamWaitEvent(s2, ev[0], 0);

    // s1: bev patch-embed chain
    convert_h_k<<<2048, 256, 0, s1>>>(pe_bev_w, wb, HC_*KBEV_/4);
    im2col_h_k<BC_><<<dim3(Hg_, BC_, B_), 256, 0, s1>>>(bev, imb);
    gfh_k<0u,4><<<dim3(2, 25, 4), 256, NSTG*HSTG, s1>>>(imb, wb, nullptr, part, nullptr,
                                                        HC_, KBEV_, 0);
    add_pos_ln_red_k<4><<<MT_, 256, 0, s1>>>(part, pe_bev_b, pos_bev, ln_bev_g, ln_bev_b, tgt);
    cudaEventRecord(ev[1], s1);

    // s2: prior patch-embed chain
    convert_h_k<<<512, 256, 0, s2>>>(pe_pr_w, wp, HC_*KPR_/4);
    im2col_h_k<PC_><<<dim3(Hg_, PC_, B_), 256, 0, s2>>>(prior, imp);
    gfh_k<0u,4><<<dim3(2, 25, 4), 256, NSTG*HSTG, s2>>>(imp, wp, nullptr, part2, nullptr,
                                                        HC_, KPR_, 0);
    add_pos_ln_red_k<4><<<MT_, 256, 0, s2>>>(part2, pe_pr_b, pos_pr, ln_pr_g, ln_pr_b, pr);
    cudaEventRecord(ev[2], s2);

    // s0: independent weight prep
    convert_h_k<<<256, 256>>>(fc1_w, fc116, 2*MLPD_*HC_/4);
    convert_h_k<<<256, 256>>>(fc2_w, fc216, 2*HC_*MLPD_/4);
    convert_h_k<<<64, 256>>>(vp_w, vp16, 2*HC_*HC_/4);
    convert_h_k<<<64, 256>>>(op_w, op16, 2*HC_*HC_/4);
    convert_h_k<<<2048, 256>>>(expand_w, we, NEXP_*HC_/4);
    concat_ow_h_k<<<dim3(NOA_, 2), 256>>>(off_w, off_b, aw_w, aw_b, oaw16, oab);

    // join
    cudaStreamWaitEvent(0, ev[1], 0);
    cudaStreamWaitEvent(0, ev[2], 0);

    // ---- decoder layers ----
    for (int l = 0; l < 2; l++) {
        int eb = 4 + l * 4;
        ln2_k<<<dim3(MT_, 2), 256>>>(tgt, t, pr, s, n1_g + l * HC_, n1_b + l * HC_);

        cudaEventRecord(ev[eb], 0);
        cudaStreamWaitEvent(s1, ev[eb], 0);
        mma_gemm_h_k<0,0><<<dim3(4, 50), 128, 0, s1>>>(
            s, vp16 + (size_t)l * HC_ * HC_, vp_b + l * HC_, nullptr, val, nullptr, HC_, HC_);
        cudaEventRecord(ev[eb + 1], s1);
        mma_gemm_h_k<0,0><<<dim3(3, 50), 128>>>(
            t, oaw16 + (size_t)l * NOA_ * HC_, oab + l * NOA_, nullptr, oa, nullptr, NOA_, HC_);
        cudaStreamWaitEvent(0, ev[eb + 1], 0);

        deform_k<<<MT_, 256>>>(val, oa, attn);

        mma_gemm_h_k<1,0><<<dim3(4, 50), 128>>>(
            attn, op16 + (size_t)l * HC_ * HC_, op_b + l * HC_, tgt, tgt, nullptr, HC_, HC_);

        ln_h_k<<<MT_, 256>>>(tgt, n2_g + l * HC_, n2_b + l * HC_, t16);
        gfh_k<FB_BIAS|FB_GELU|FB_F32,1><<<dim3(8, 25), 256, NSTG*HSTG>>>(
            t16, fc116 + (size_t)l * MLPD_ * HC_, fc1_b + l * MLPD_,
            mlp, nullptr, MLPD_, HC_, 0);
        if (l == 1) {
            // final fc2: also emit fp16 tgt for expand
            mma_gemm_h_k<1,1><<<dim3(4, 50), 128>>>(
                mlp, fc216 + (size_t)l * HC_ * MLPD_, fc2_b + l * HC_, tgt, tgt, tg16, HC_, MLPD_);
        } else {
            mma_gemm_h_k<1,0><<<dim3(4, 50), 128>>>(
                mlp, fc216 + (size_t)l * HC_ * MLPD_, fc2_b + l * HC_, tgt, tgt, nullptr, HC_, MLPD_);
        }
    }

    // ---- expand: fp16 GEMM halves pipelined with scatter halves ----
    gfh_k<FB_HALF,1><<<dim3(NEXP_/128, 13), 256, NSTG*HSTG>>>(
        tg16, we, nullptr, nullptr, exph, NEXP_, HC_, 0);
    cudaEventRecord(ev[12], 0);
    gfh_k<FB_HALF,1><<<dim3(NEXP_/128, 12), 256, NSTG*HSTG>>>(
        tg16, we, nullptr, nullptr, exph, NEXP_, HC_, 13);
    cudaStreamWaitEvent(s1, ev[12], 0);
    expand_scatter_k<<<dim3(16, 10, 41), 256, 0, s1>>>(exph, bev, out, 0);
    cudaEventRecord(ev[13], s1);
    expand_scatter_k<<<dim3(16, 10, 39), 256>>>(exph, bev, out, 41);
    cudaStreamWaitEvent(0, ev[13], 0);
}

// round 16
// speedup vs baseline: 1.0053x; 1.0053x over previous
#include <cuda_runtime.h>
#include <cuda_bf16.h>
#include <cuda_fp16.h>
#include <stdint.h>
#include <math.h>

// ---------------- static config ----------------
#define B_    4
#define BC_   256
#define PC_   64
#define HC_   256
#define H_    200
#define W_    400
#define P_    10
#define Hg_   20
#define Wg_   40
#define LQ_   800
#define MT_   (B_*LQ_)     // 3200 rows
#define NH_   8
#define NP_   8
#define DH_   32
#define MLPD_ 1024
#define NEXP_ 25600
#define KBEV_ 25600
#define KPR_  6400
#define NOA_  192

// ---------------- scratch ----------------
__device__ float g_tgt [MT_*HC_];
__device__ float g_pr  [MT_*HC_];
__device__ float g_t   [MT_*HC_];
__device__ float g_s   [MT_*HC_];
__device__ float g_val [MT_*HC_];
__device__ float g_attn[MT_*HC_];
__device__ float g_oa  [MT_*NOA_];
__device__ float g_mlp [MT_*MLPD_];
__device__ float g_part [4*MT_*HC_];
__device__ float g_part2[4*MT_*HC_];
__device__ float g_oab [2*NOA_];
__device__ __half g_exph[(size_t)MT_*NEXP_];

// fp16 planes
__device__ __align__(256) __half g_imb [(size_t)MT_*KBEV_];
__device__ __align__(256) __half g_imp [(size_t)MT_*KPR_];
__device__ __align__(256) __half g_wb  [HC_*KBEV_];
__device__ __align__(256) __half g_wp  [HC_*KPR_];
__device__ __align__(256) __half g_we  [NEXP_*HC_];
__device__ __align__(256) __half g_tg16[MT_*HC_];
__device__ __align__(256) __half g_t16 [MT_*HC_];
__device__ __align__(256) __half g_fc116[2*MLPD_*HC_];
__device__ __align__(256) __half g_fc216[2*HC_*MLPD_];
__device__ __align__(256) __half g_vp16 [2*HC_*HC_];
__device__ __align__(256) __half g_op16 [2*HC_*HC_];
__device__ __align__(256) __half g_oaw16[2*NOA_*HC_];

// ---------------- helpers ----------------
__device__ __forceinline__ float gelu_exact(float x) {
    return 0.5f * x * (1.0f + erff(x * 0.70710678118654752f));
}
__device__ __forceinline__ unsigned h2u(__half2 h) {
    return *reinterpret_cast<unsigned*>(&h);
}
__device__ __forceinline__ void mma_f16(float* c,
                                        unsigned a0, unsigned a1, unsigned a2, unsigned a3,
                                        unsigned b0, unsigned b1) {
    asm volatile(
        "mma.sync.aligned.m16n8k16.row.col.f32.f16.f16.f32 "
        "{%0,%1,%2,%3}, {%4,%5,%6,%7}, {%8,%9}, {%0,%1,%2,%3};\n"
        : "+f"(c[0]), "+f"(c[1]), "+f"(c[2]), "+f"(c[3])
        : "r"(a0), "r"(a1), "r"(a2), "r"(a3), "r"(b0), "r"(b1));
}
__device__ __forceinline__ unsigned smem_u32(const void* p) {
    return (unsigned)__cvta_generic_to_shared(p);
}
__device__ __forceinline__ void cp16(unsigned s, const void* g) {
    asm volatile("cp.async.cg.shared.global [%0], [%1], 16;" :: "r"(s), "l"(g));
}
__device__ __forceinline__ void cp_commit() { asm volatile("cp.async.commit_group;"); }
template<int NN> __device__ __forceinline__ void cp_wait() {
    asm volatile("cp.async.wait_group %0;" :: "n"(NN));
}
__device__ __forceinline__ void ldsm4(unsigned &r0, unsigned &r1, unsigned &r2, unsigned &r3,
                                      unsigned addr) {
    asm volatile("ldmatrix.sync.aligned.m8n8.x4.shared.b16 {%0,%1,%2,%3}, [%4];"
                 : "=r"(r0), "=r"(r1), "=r"(r2), "=r"(r3) : "r"(addr));
}

// ==========================================================================
// converts
// ==========================================================================
__global__ void convert_h_k(const float* __restrict__ X,
                            __half* __restrict__ Ph, int n4) {
    for (int i = blockIdx.x * blockDim.x + threadIdx.x; i < n4; i += gridDim.x * blockDim.x) {
        float4 v = ((const float4*)X)[i];
        ((__half2*)Ph)[i * 2]     = __floats2half2_rn(v.x, v.y);
        ((__half2*)Ph)[i * 2 + 1] = __floats2half2_rn(v.z, v.w);
    }
}

__global__ void concat_ow_h_k(const float* __restrict__ off_w, const float* __restrict__ off_b,
                              const float* __restrict__ aw_w,  const float* __restrict__ aw_b,
                              __half* __restrict__ Wc, float* __restrict__ Bc) {
    int n = blockIdx.x, l = blockIdx.y, c = threadIdx.x;
    const float* src = (n < 128) ? off_w + (size_t)(l * 128 + n) * HC_
                                 : aw_w  + (size_t)(l * 64 + (n - 128)) * HC_;
    Wc[(size_t)(l * NOA_ + n) * HC_ + c] = __float2half_rn(src[c]);
    if (c == 0)
        Bc[l * NOA_ + n] = (n < 128) ? off_b[l * 128 + n] : aw_b[l * 64 + n - 128];
}

// ==========================================================================
// im2col -> fp16 plane
// ==========================================================================
template<int CIN>
__global__ void im2col_h_k(const float* __restrict__ X,
                           __half* __restrict__ Ph) {
    __shared__ float s[4000];
    int hg = blockIdx.x, ci = blockIdx.y, b = blockIdx.z;
    int tid = threadIdx.x;
    const int K = CIN * 100;
    const float* src = X + ((size_t)(b * CIN + ci) * H_ + hg * P_) * W_;
    for (int i = tid; i < 4000; i += 256) s[i] = src[i];
    __syncthreads();
    size_t rowbase = (size_t)(b * LQ_ + hg * Wg_);
    for (int j = tid; j < 4000; j += 256) {
        int wg = j / 100, idx = j - wg * 100;
        int py = idx / 10, px = idx - py * 10;
        Ph[(rowbase + wg) * K + ci * 100 + idx] = __float2half_rn(s[py * 400 + wg * 10 + px]);
    }
}

// ==========================================================================
// fp16 mma.sync fast GEMM, 128x128x32, 2-stage cp.async (best-known config)
// ==========================================================================
#define FB_BIAS 1u
#define FB_GELU 2u
#define FB_F32  4u
#define FB_HALF 8u
#define HSTG 20480

template<unsigned MODE, int SPLIT>
__global__ void __launch_bounds__(256) gfh_k(
        const __half* __restrict__ A_g, const __half* __restrict__ B_g,
        const float* __restrict__ bias, float* __restrict__ C, __half* __restrict__ Ch,
        int N, int K, int y_off) {
    extern __shared__ char smraw[];
    unsigned sbase = smem_u32(smraw);

    int tid = threadIdx.x, warp = tid >> 5, lane = tid & 31;
    int m0 = (blockIdx.y + y_off) * 128, n0 = blockIdx.x * 128;
    int Kc = K / SPLIT;
    int kstart = (SPLIT > 1) ? blockIdx.z * Kc : 0;
    int nk = Kc / 32;
    int wm = (warp >> 2) * 64, wn = (warp & 3) * 32;
    int gid = lane >> 2, tig = lane & 3;

    float acc[4][4][4];
#pragma unroll
    for (int mi = 0; mi < 4; mi++)
#pragma unroll
        for (int ni = 0; ni < 4; ni++)
#pragma unroll
            for (int q = 0; q < 4; q++) acc[mi][ni][q] = 0.f;

    auto load_tile = [&](int kt, int st) {
        int kb = kstart + kt * 32;
        unsigned sb = sbase + st * HSTG;
#pragma unroll
        for (int j = 0; j < 2; j++) {
            int c = j * 256 + tid;
            int row = c >> 2, q = c & 3;
            unsigned so = row * 80 + q * 16;
            cp16(sb +         so, A_g + (size_t)(m0 + row) * K + kb + q * 8);
            cp16(sb + 10240 + so, B_g + (size_t)(n0 + row) * K + kb + q * 8);
        }
    };

    auto compute = [&](int st) {
        unsigned sb = sbase + st * HSTG;
#pragma unroll
        for (int s = 0; s < 2; s++) {
            unsigned ah[4][4], bh[4][2];
            int arow = wm + (lane & 15);
            unsigned abyte = ((lane >> 4) * 16) + s * 32;
#pragma unroll
            for (int mi = 0; mi < 4; mi++) {
                unsigned ad = sb + (arow + mi * 16) * 80 + abyte;
                ldsm4(ah[mi][0], ah[mi][1], ah[mi][2], ah[mi][3], ad);
            }
            int q = lane >> 3, r = lane & 7;
            int brow = wn + ((q >> 1) << 3) + r;
            unsigned bbyte = (q & 1) * 16 + s * 32;
#pragma unroll
            for (int nj = 0; nj < 2; nj++) {
                unsigned bd = sb + 10240 + (brow + nj * 16) * 80 + bbyte;
                unsigned r0, r1, r2, r3;
                ldsm4(r0, r1, r2, r3, bd);
                bh[nj*2][0] = r0; bh[nj*2][1] = r1; bh[nj*2+1][0] = r2; bh[nj*2+1][1] = r3;
            }
#pragma unroll
            for (int mi = 0; mi < 4; mi++)
#pragma unroll
                for (int ni = 0; ni < 4; ni++)
                    mma_f16(acc[mi][ni], ah[mi][0], ah[mi][1], ah[mi][2], ah[mi][3],
                            bh[ni][0], bh[ni][1]);
        }
    };

    load_tile(0, 0);
    cp_commit();
    for (int kt = 0; kt < nk; kt++) {
        if (kt + 1 < nk) {
            load_tile(kt + 1, (kt + 1) & 1);
            cp_commit();
            cp_wait<1>();
        } else {
            cp_wait<0>();
        }
        __syncthreads();
        compute(kt & 1);
        __syncthreads();
    }

#pragma unroll
    for (int mi = 0; mi < 4; mi++) {
#pragma unroll
        for (int ni = 0; ni < 4; ni++) {
            int m = m0 + wm + mi * 16 + gid;
            int n = n0 + wn + ni * 8 + tig * 2;
            float v0 = acc[mi][ni][0], v1 = acc[mi][ni][1];
            float v2 = acc[mi][ni][2], v3 = acc[mi][ni][3];
            if (SPLIT > 1) {
                float* Cp = C + (size_t)blockIdx.z * ((size_t)MT_ * N);
                Cp[(size_t)m * N + n] = v0;       Cp[(size_t)m * N + n + 1] = v1;
                Cp[(size_t)(m + 8) * N + n] = v2; Cp[(size_t)(m + 8) * N + n + 1] = v3;
            } else {
                if (MODE & FB_BIAS) {
                    float b0 = bias[n], b1 = bias[n + 1];
                    v0 += b0; v1 += b1; v2 += b0; v3 += b1;
                }
                if (MODE & FB_GELU) {
                    v0 = gelu_exact(v0); v1 = gelu_exact(v1);
                    v2 = gelu_exact(v2); v3 = gelu_exact(v3);
                }
                size_t o0 = (size_t)m * N + n, o1 = (size_t)(m + 8) * N + n;
                if (MODE & FB_F32) {
                    C[o0] = v0; C[o0 + 1] = v1; C[o1] = v2; C[o1 + 1] = v3;
                }
                if (MODE & FB_HALF) {
                    Ch[o0] = __float2half(v0); Ch[o0 + 1] = __float2half(v1);
                    Ch[o1] = __float2half(v2); Ch[o1 + 1] = __float2half(v3);
                }
            }
        }
    }
}

// ==========================================================================
// Slow-path fp16 NT GEMM: A fp32 inline->fp16, B pre-fp16. 64x64, 128 thr.
// WRITE_H: also emit fp16 copy of result (final tgt -> expand input).
// ==========================================================================
#define SSTR 20
template<int HAS_RES, int WRITE_H>
__global__ __launch_bounds__(128) void mma_gemm_h_k(
        const float* __restrict__ A, const __half* __restrict__ B_g,
        const float* __restrict__ bias, const float* __restrict__ R,
        float* __restrict__ C, __half* __restrict__ Ch, int N, int K) {
    __shared__ unsigned Ah[64*SSTR], Bh[64*SSTR];
    int tid  = threadIdx.x;
    int warp = tid >> 5, lane = tid & 31;
    int gid  = lane >> 2, tig = lane & 3;
    int m0 = blockIdx.y * 64, n0 = blockIdx.x * 64;
    int wm = (warp & 1) * 32, wn = (warp >> 1) * 32;

    int row = tid >> 1, half = tid & 1;
    const float* ap = A + (size_t)(m0 + row) * K + half * 16;
    const __half* bp = B_g + (size_t)(n0 + row) * K + half * 16;

    float4 fa[4];
    uint4 fb[2];
#pragma unroll
    for (int i = 0; i < 4; i++) fa[i] = *(const float4*)(ap + i * 4);
#pragma unroll
    for (int i = 0; i < 2; i++) fb[i] = *(const uint4*)(bp + i * 8);

    float acc[2][4][4];
#pragma unroll
    for (int mi = 0; mi < 2; mi++)
#pragma unroll
        for (int ni = 0; ni < 4; ni++)
#pragma unroll
            for (int q = 0; q < 4; q++) acc[mi][ni][q] = 0.f;

    for (int k0 = 0; k0 < K; k0 += 32) {
        int sb = row * SSTR + half * 8;
#pragma unroll
        for (int i = 0; i < 4; i++) {
            Ah[sb + i*2]     = h2u(__floats2half2_rn(fa[i].x, fa[i].y));
            Ah[sb + i*2 + 1] = h2u(__floats2half2_rn(fa[i].z, fa[i].w));
        }
        Bh[sb + 0] = fb[0].x; Bh[sb + 1] = fb[0].y;
        Bh[sb + 2] = fb[0].z; Bh[sb + 3] = fb[0].w;
        Bh[sb + 4] = fb[1].x; Bh[sb + 5] = fb[1].y;
        Bh[sb + 6] = fb[1].z; Bh[sb + 7] = fb[1].w;
        __syncthreads();
        if (k0 + 32 < K) {
#pragma unroll
            for (int i = 0; i < 4; i++) fa[i] = *(const float4*)(ap + k0 + 32 + i * 4);
#pragma unroll
            for (int i = 0; i < 2; i++) fb[i] = *(const uint4*)(bp + k0 + 32 + i * 8);
        }
#pragma unroll
        for (int s = 0; s < 2; s++) {
            unsigned ah[2][4], bh[4][2];
            int p = s * 8 + tig;
#pragma unroll
            for (int mi = 0; mi < 2; mi++) {
                int r0 = (wm + mi * 16 + gid) * SSTR;
                int r8 = r0 + 8 * SSTR;
                ah[mi][0] = Ah[r0 + p];     ah[mi][1] = Ah[r8 + p];
                ah[mi][2] = Ah[r0 + p + 4]; ah[mi][3] = Ah[r8 + p + 4];
            }
#pragma unroll
            for (int ni = 0; ni < 4; ni++) {
                int nr = (wn + ni * 8 + gid) * SSTR;
                bh[ni][0] = Bh[nr + p]; bh[ni][1] = Bh[nr + p + 4];
            }
#pragma unroll
            for (int mi = 0; mi < 2; mi++)
#pragma unroll
                for (int ni = 0; ni < 4; ni++)
                    mma_f16(acc[mi][ni], ah[mi][0], ah[mi][1], ah[mi][2], ah[mi][3],
                            bh[ni][0], bh[ni][1]);
        }
        __syncthreads();
    }
#pragma unroll
    for (int mi = 0; mi < 2; mi++) {
#pragma unroll
        for (int ni = 0; ni < 4; ni++) {
            int m = m0 + wm + mi * 16 + gid;
            int n = n0 + wn + ni * 8 + tig * 2;
            float b0v = bias[n], b1v = bias[n + 1];
            float v0 = acc[mi][ni][0] + b0v, v1 = acc[mi][ni][1] + b1v;
            float v2 = acc[mi][ni][2] + b0v, v3 = acc[mi][ni][3] + b1v;
            if (HAS_RES) {
                const float* rp = R + (size_t)m * N + n;
                v0 += rp[0]; v1 += rp[1];
                v2 += rp[(size_t)8 * N]; v3 += rp[(size_t)8 * N + 1];
            }
            float* cp = C + (size_t)m * N + n;
            cp[0] = v0; cp[1] = v1;
            cp[(size_t)8 * N] = v2; cp[(size_t)8 * N + 1] = v3;
            if (WRITE_H) {
                __half* hp = Ch + (size_t)m * N + n;
                hp[0] = __float2half_rn(v0); hp[1] = __float2half_rn(v1);
                hp[(size_t)8 * N] = __float2half_rn(v2);
                hp[(size_t)8 * N + 1] = __float2half_rn(v3);
            }
        }
    }
}

// ==========================================================================
// Expand scatter (fp16 temp -> fp32 out, + bev residual), z_off for split
// ==========================================================================
__global__ void expand_scatter_k(const __half* __restrict__ T,
                                 const float* __restrict__ bev,
                                 float* __restrict__ out, int z_off) {
    __shared__ float s[400][17];
    int bcg = blockIdx.x, py = blockIdx.y, bz = blockIdx.z + z_off;
    int b = bz / 20, hg = bz % 20;
    int tid = threadIdx.x;
    int mbase = b * LQ_ + hg * Wg_;
    const __half* tb = T + (size_t)mbase * NEXP_ + py * 2560 + bcg * 16;

#pragma unroll
    for (int it = 0; it < 25; it++) {
        int j = it * 256 + tid;
        int unit = j >> 4, bcl = j & 15;
        int wg = unit / 10, px = unit - wg * 10;
        s[unit][bcl] = __half2float(tb[(size_t)wg * NEXP_ + px * 256 + bcl]);
    }
    __syncthreads();

    int rowbase = hg * P_ + py;
#pragma unroll
    for (int it = 0; it < 25; it++) {
        int j = it * 256 + tid;
        int bcl = j / 400, pix = j - bcl * 400;
        int ch = bcg * 16 + bcl;
        size_t gi = (((size_t)b * BC_ + ch) * H_ + rowbase) * W_ + pix;
        out[gi] = s[pix][bcl] + bev[gi];
    }
}

// ==========================================================================
// LayerNorm family
// ==========================================================================
__device__ __forceinline__ float block_ln_val(float x, const float* __restrict__ g,
                                              const float* __restrict__ bt, int c) {
    __shared__ float red[2][8];
    float s = x, sq = x * x;
#pragma unroll
    for (int o = 16; o > 0; o >>= 1) {
        s  += __shfl_down_sync(0xffffffffu, s, o);
        sq += __shfl_down_sync(0xffffffffu, sq, o);
    }
    int w = c >> 5, lane = c & 31;
    if (lane == 0) { red[0][w] = s; red[1][w] = sq; }
    __syncthreads();
    float ts = 0.f, tq = 0.f;
#pragma unroll
    for (int i = 0; i < 8; i++) { ts += red[0][i]; tq += red[1][i]; }
    float mean = ts * (1.0f / HC_);
    float var  = tq * (1.0f / HC_) - mean * mean;
    float inv  = rsqrtf(var + 1e-5f);
    return (x - mean) * inv * g[c] + bt[c];
}

template<int SPLIT>
__global__ void add_pos_ln_red_k(const float* __restrict__ part,
                                 const float* __restrict__ cb,
                                 const float* __restrict__ pos,
                                 const float* __restrict__ g,
                                 const float* __restrict__ bt,
                                 float* __restrict__ Y) {
    int row = blockIdx.x, c = threadIdx.x;
    float x = 0.f;
#pragma unroll
    for (int z = 0; z < SPLIT; z++) x += part[(size_t)z * MT_ * HC_ + (size_t)row * HC_ + c];
    x += cb[c] + pos[(row % LQ_) * HC_ + c];
    Y[(size_t)row * HC_ + c] = block_ln_val(x, g, bt, c);
}

__global__ void ln2_k(const float* __restrict__ X0, float* __restrict__ Y0,
                      const float* __restrict__ X1, float* __restrict__ Y1,
                      const float* __restrict__ g, const float* __restrict__ bt) {
    int row = blockIdx.x, c = threadIdx.x;
    const float* X = blockIdx.y ? X1 : X0;
    float* Y = blockIdx.y ? Y1 : Y0;
    float x = X[(size_t)row * HC_ + c];
    Y[(size_t)row * HC_ + c] = block_ln_val(x, g, bt, c);
}

__global__ void ln_h_k(const float* __restrict__ X,
                       const float* __restrict__ g,
                       const float* __restrict__ bt,
                       __half* __restrict__ Y) {
    int row = blockIdx.x, c = threadIdx.x;
    float x = X[(size_t)row * HC_ + c];
    Y[(size_t)row * HC_ + c] = __float2half_rn(block_ln_val(x, g, bt, c));
}

// ==========================================================================
// Deformable attention
// ==========================================================================
__global__ void deform_k(const float* __restrict__ val,
                         const float* __restrict__ oa,
                         float* __restrict__ attn) {
    int row  = blockIdx.x;
    int h    = threadIdx.x >> 5;
    int lane = threadIdx.x & 31;
    int b = row / LQ_, l = row % LQ_;
    int hg = l / Wg_, wg = l % Wg_;

    float refx = ((float)wg + 0.5f) / (float)Wg_;
    float refy = ((float)hg + 0.5f) / (float)Hg_;

    const float* oarow = oa + (size_t)row * NOA_;
    float lg[NP_];
    float mx = -1e30f;
#pragma unroll
    for (int p = 0; p < NP_; p++) {
        lg[p] = oarow[128 + h * NP_ + p];
        mx = fmaxf(mx, lg[p]);
    }
    float den = 0.f;
#pragma unroll
    for (int p = 0; p < NP_; p++) { lg[p] = expf(lg[p] - mx); den += lg[p]; }
    float invden = 1.0f / den;

    const float* vb = val + (size_t)b * LQ_ * HC_ + h * DH_ + lane;
    float acc = 0.f;

#pragma unroll
    for (int p = 0; p < NP_; p++) {
        float ox = oarow[(h * NP_ + p) * 2 + 0];
        float oy = oarow[(h * NP_ + p) * 2 + 1];
        float x = (refx + ox * (1.0f / Wg_)) * (float)Wg_ - 0.5f;
        float y = (refy + oy * (1.0f / Hg_)) * (float)Hg_ - 0.5f;
        float xf = floorf(x), yf = floorf(y);
        int x0 = (int)xf, y0 = (int)yf;
        float lx = x - xf, ly = y - yf;
        float wp = lg[p] * invden;

        float w00 = (1.f - lx) * (1.f - ly);
        float w10 = lx * (1.f - ly);
        float w01 = (1.f - lx) * ly;
        float w11 = lx * ly;

        if (x0     >= 0 && x0     < Wg_ && y0     >= 0 && y0     < Hg_)
            acc = fmaf(wp * w00, vb[(size_t)(y0 * Wg_ + x0) * HC_], acc);
        if (x0 + 1 >= 0 && x0 + 1 < Wg_ && y0     >= 0 && y0     < Hg_)
            acc = fmaf(wp * w10, vb[(size_t)(y0 * Wg_ + x0 + 1) * HC_], acc);
        if (x0     >= 0 && x0     < Wg_ && y0 + 1 >= 0 && y0 + 1 < Hg_)
            acc = fmaf(wp * w01, vb[(size_t)((y0 + 1) * Wg_ + x0) * HC_], acc);
        if (x0 + 1 >= 0 && x0 + 1 < Wg_ && y0 + 1 >= 0 && y0 + 1 < Hg_)
            acc = fmaf(wp * w11, vb[(size_t)((y0 + 1) * Wg_ + x0 + 1) * HC_], acc);
    }
    attn[(size_t)row * HC_ + h * DH_ + lane] = acc;
}

// ==========================================================================
// host launch
// ==========================================================================
extern "C" void kernel_launch(void* const* d_in, const int* in_sizes, int n_in,
                              void* d_out, int out_size) {
    const float* bev      = (const float*)d_in[0];
    const float* prior    = (const float*)d_in[1];
    const float* pe_bev_w = (const float*)d_in[2];
    const float* pe_bev_b = (const float*)d_in[3];
    const float* pe_pr_w  = (const float*)d_in[4];
    const float* pe_pr_b  = (const float*)d_in[5];
    const float* pos_bev  = (const float*)d_in[6];
    const float* pos_pr   = (const float*)d_in[7];
    const float* ln_bev_g = (const float*)d_in[8];
    const float* ln_bev_b = (const float*)d_in[9];
    const float* ln_pr_g  = (const float*)d_in[10];
    const float* ln_pr_b  = (const float*)d_in[11];
    const float* n1_g     = (const float*)d_in[12];
    const float* n1_b     = (const float*)d_in[13];
    const float* n2_g     = (const float*)d_in[14];
    const float* n2_b     = (const float*)d_in[15];
    const float* off_w    = (const float*)d_in[16];
    const float* off_b    = (const float*)d_in[17];
    const float* aw_w     = (const float*)d_in[18];
    const float* aw_b     = (const float*)d_in[19];
    const float* vp_w     = (const float*)d_in[20];
    const float* vp_b     = (const float*)d_in[21];
    const float* op_w     = (const float*)d_in[22];
    const float* op_b     = (const float*)d_in[23];
    const float* fc1_w    = (const float*)d_in[24];
    const float* fc1_b    = (const float*)d_in[25];
    const float* fc2_w    = (const float*)d_in[26];
    const float* fc2_b    = (const float*)d_in[27];
    const float* expand_w = (const float*)d_in[28];
    float* out = (float*)d_out;

    float *tgt, *pr, *t, *s, *val, *attn, *oa, *mlp, *part, *part2, *oab;
    __half *exph, *imb, *imp, *wb, *wp, *we, *tg16, *t16;
    __half *fc116, *fc216, *vp16, *op16, *oaw16;
    cudaGetSymbolAddress((void**)&tgt,  g_tgt);
    cudaGetSymbolAddress((void**)&pr,   g_pr);
    cudaGetSymbolAddress((void**)&t,    g_t);
    cudaGetSymbolAddress((void**)&s,    g_s);
    cudaGetSymbolAddress((void**)&val,  g_val);
    cudaGetSymbolAddress((void**)&attn, g_attn);
    cudaGetSymbolAddress((void**)&oa,   g_oa);
    cudaGetSymbolAddress((void**)&mlp,  g_mlp);
    cudaGetSymbolAddress((void**)&part, g_part);
    cudaGetSymbolAddress((void**)&part2,g_part2);
    cudaGetSymbolAddress((void**)&oab,  g_oab);
    cudaGetSymbolAddress((void**)&exph, g_exph);
    cudaGetSymbolAddress((void**)&imb,  g_imb);
    cudaGetSymbolAddress((void**)&imp,  g_imp);
    cudaGetSymbolAddress((void**)&wb,   g_wb);
    cudaGetSymbolAddress((void**)&wp,   g_wp);
    cudaGetSymbolAddress((void**)&we,   g_we);
    cudaGetSymbolAddress((void**)&tg16, g_tg16);
    cudaGetSymbolAddress((void**)&t16,  g_t16);
    cudaGetSymbolAddress((void**)&fc116,g_fc116);
    cudaGetSymbolAddress((void**)&fc216,g_fc216);
    cudaGetSymbolAddress((void**)&vp16, g_vp16);
    cudaGetSymbolAddress((void**)&op16, g_op16);
    cudaGetSymbolAddress((void**)&oaw16,g_oaw16);

    cudaFuncSetAttribute(gfh_k<0u,4>, cudaFuncAttributeMaxDynamicSharedMemorySize, 2*HSTG);
    cudaFuncSetAttribute(gfh_k<FB_HALF,1>, cudaFuncAttributeMaxDynamicSharedMemorySize, 2*HSTG);
    cudaFuncSetAttribute(gfh_k<FB_BIAS|FB_GELU|FB_F32,1>, cudaFuncAttributeMaxDynamicSharedMemorySize, 2*HSTG);

    static cudaStream_t s1 = nullptr, s2 = nullptr;
    static cudaEvent_t ev[16];
    if (!s1) {
        cudaStreamCreateWithFlags(&s1, cudaStreamNonBlocking);
        cudaStreamCreateWithFlags(&s2, cudaStreamNonBlocking);
        for (int i = 0; i < 16; i++) cudaEventCreateWithFlags(&ev[i], cudaEventDisableTiming);
    }

    // ---- fork ----
    cudaEventRecord(ev[0], 0);
    cudaStreamWaitEvent(s1, ev[0], 0);
    cudaStreamWaitEvent(s2, ev[0], 0);

    // s1: bev patch-embed chain
    convert_h_k<<<2048, 256, 0, s1>>>(pe_bev_w, wb, HC_*KBEV_/4);
    im2col_h_k<BC_><<<dim3(Hg_, BC_, B_), 256, 0, s1>>>(bev, imb);
    gfh_k<0u,4><<<dim3(2, 25, 4), 256, 2*HSTG, s1>>>(imb, wb, nullptr, part, nullptr,
                                                     HC_, KBEV_, 0);
    add_pos_ln_red_k<4><<<MT_, 256, 0, s1>>>(part, pe_bev_b, pos_bev, ln_bev_g, ln_bev_b, tgt);
    cudaEventRecord(ev[1], s1);

    // s2: prior patch-embed chain
    convert_h_k<<<512, 256, 0, s2>>>(pe_pr_w, wp, HC_*KPR_/4);
    im2col_h_k<PC_><<<dim3(Hg_, PC_, B_), 256, 0, s2>>>(prior, imp);
    gfh_k<0u,4><<<dim3(2, 25, 4), 256, 2*HSTG, s2>>>(imp, wp, nullptr, part2, nullptr,
                                                     HC_, KPR_, 0);
    add_pos_ln_red_k<4><<<MT_, 256, 0, s2>>>(part2, pe_pr_b, pos_pr, ln_pr_g, ln_pr_b, pr);
    cudaEventRecord(ev[2], s2);

    // s0: independent weight prep
    convert_h_k<<<256, 256>>>(fc1_w, fc116, 2*MLPD_*HC_/4);
    convert_h_k<<<256, 256>>>(fc2_w, fc216, 2*HC_*MLPD_/4);
    convert_h_k<<<64, 256>>>(vp_w, vp16, 2*HC_*HC_/4);
    convert_h_k<<<64, 256>>>(op_w, op16, 2*HC_*HC_/4);
    convert_h_k<<<2048, 256>>>(expand_w, we, NEXP_*HC_/4);
    concat_ow_h_k<<<dim3(NOA_, 2), 256>>>(off_w, off_b, aw_w, aw_b, oaw16, oab);

    // join
    cudaStreamWaitEvent(0, ev[1], 0);
    cudaStreamWaitEvent(0, ev[2], 0);

    // ---- decoder layers ----
    for (int l = 0; l < 2; l++) {
        int eb = 4 + l * 4;
        ln2_k<<<dim3(MT_, 2), 256>>>(tgt, t, pr, s, n1_g + l * HC_, n1_b + l * HC_);

        cudaEventRecord(ev[eb], 0);
        cudaStreamWaitEvent(s1, ev[eb], 0);
        mma_gemm_h_k<0,0><<<dim3(4, 50), 128, 0, s1>>>(
            s, vp16 + (size_t)l * HC_ * HC_, vp_b + l * HC_, nullptr, val, nullptr, HC_, HC_);
        cudaEventRecord(ev[eb + 1], s1);
        mma_gemm_h_k<0,0><<<dim3(3, 50), 128>>>(
            t, oaw16 + (size_t)l * NOA_ * HC_, oab + l * NOA_, nullptr, oa, nullptr, NOA_, HC_);
        cudaStreamWaitEvent(0, ev[eb + 1], 0);

        deform_k<<<MT_, 256>>>(val, oa, attn);

        mma_gemm_h_k<1,0><<<dim3(4, 50), 128>>>(
            attn, op16 + (size_t)l * HC_ * HC_, op_b + l * HC_, tgt, tgt, nullptr, HC_, HC_);

        ln_h_k<<<MT_, 256>>>(tgt, n2_g + l * HC_, n2_b + l * HC_, t16);
        gfh_k<FB_BIAS|FB_GELU|FB_F32,1><<<dim3(8, 25), 256, 2*HSTG>>>(
            t16, fc116 + (size_t)l * MLPD_ * HC_, fc1_b + l * MLPD_,
            mlp, nullptr, MLPD_, HC_, 0);
        if (l == 1) {
            mma_gemm_h_k<1,1><<<dim3(4, 50), 128>>>(
                mlp, fc216 + (size_t)l * HC_ * MLPD_, fc2_b + l * HC_, tgt, tgt, tg16, HC_, MLPD_);
        } else {
            mma_gemm_h_k<1,0><<<dim3(4, 50), 128>>>(
                mlp, fc216 + (size_t)l * HC_ * MLPD_, fc2_b + l * HC_, tgt, tgt, nullptr, HC_, MLPD_);
        }
    }

    // ---- expand: fp16 GEMM halves pipelined with scatter halves ----
    gfh_k<FB_HALF,1><<<dim3(NEXP_/128, 13), 256, 2*HSTG>>>(
        tg16, we, nullptr, nullptr, exph, NEXP_, HC_, 0);
    cudaEventRecord(ev[12], 0);
    gfh_k<FB_HALF,1><<<dim3(NEXP_/128, 12), 256, 2*HSTG>>>(
        tg16, we, nullptr, nullptr, exph, NEXP_, HC_, 13);
    cudaStreamWaitEvent(s1, ev[12], 0);
    expand_scatter_k<<<dim3(16, 10, 41), 256, 0, s1>>>(exph, bev, out, 0);
    cudaEventRecord(ev[13], s1);
    expand_scatter_k<<<dim3(16, 10, 39), 256>>>(exph, bev, out, 41);
    cudaStreamWaitEvent(0, ev[13], 0);
}

// round 17
// speedup vs baseline: 1.0102x; 1.0049x over previous
#include <cuda_runtime.h>
#include <cuda_bf16.h>
#include <cuda_fp16.h>
#include <stdint.h>
#include <math.h>

// ---------------- static config ----------------
#define B_    4
#define BC_   256
#define PC_   64
#define HC_   256
#define H_    200
#define W_    400
#define P_    10
#define Hg_   20
#define Wg_   40
#define LQ_   800
#define MT_   (B_*LQ_)     // 3200 rows
#define NH_   8
#define NP_   8
#define DH_   32
#define MLPD_ 1024
#define NEXP_ 25600
#define KBEV_ 25600
#define KPR_  6400
#define NOA_  192
#define CSPL_ 8            // conv split-K

// ---------------- scratch ----------------
__device__ float g_tgt [MT_*HC_];
__device__ float g_pr  [MT_*HC_];
__device__ float g_t   [MT_*HC_];
__device__ float g_s   [MT_*HC_];
__device__ float g_val [MT_*HC_];
__device__ float g_attn[MT_*HC_];
__device__ float g_oa  [MT_*NOA_];
__device__ float g_mlp [MT_*MLPD_];
__device__ float g_part [CSPL_*MT_*HC_];
__device__ float g_part2[CSPL_*MT_*HC_];
__device__ float g_oab [2*NOA_];
__device__ __half g_exph[(size_t)MT_*NEXP_];

// fp16 planes
__device__ __align__(256) __half g_imb [(size_t)MT_*KBEV_];
__device__ __align__(256) __half g_imp [(size_t)MT_*KPR_];
__device__ __align__(256) __half g_wb  [HC_*KBEV_];
__device__ __align__(256) __half g_wp  [HC_*KPR_];
__device__ __align__(256) __half g_we  [NEXP_*HC_];
__device__ __align__(256) __half g_tg16[MT_*HC_];
__device__ __align__(256) __half g_t16 [MT_*HC_];
__device__ __align__(256) __half g_fc116[2*MLPD_*HC_];
__device__ __align__(256) __half g_fc216[2*HC_*MLPD_];
__device__ __align__(256) __half g_vp16 [2*HC_*HC_];
__device__ __align__(256) __half g_op16 [2*HC_*HC_];
__device__ __align__(256) __half g_oaw16[2*NOA_*HC_];

// ---------------- helpers ----------------
__device__ __forceinline__ float gelu_exact(float x) {
    return 0.5f * x * (1.0f + erff(x * 0.70710678118654752f));
}
__device__ __forceinline__ unsigned h2u(__half2 h) {
    return *reinterpret_cast<unsigned*>(&h);
}
__device__ __forceinline__ void mma_f16(float* c,
                                        unsigned a0, unsigned a1, unsigned a2, unsigned a3,
                                        unsigned b0, unsigned b1) {
    asm volatile(
        "mma.sync.aligned.m16n8k16.row.col.f32.f16.f16.f32 "
        "{%0,%1,%2,%3}, {%4,%5,%6,%7}, {%8,%9}, {%0,%1,%2,%3};\n"
        : "+f"(c[0]), "+f"(c[1]), "+f"(c[2]), "+f"(c[3])
        : "r"(a0), "r"(a1), "r"(a2), "r"(a3), "r"(b0), "r"(b1));
}
__device__ __forceinline__ unsigned smem_u32(const void* p) {
    return (unsigned)__cvta_generic_to_shared(p);
}
__device__ __forceinline__ void cp16(unsigned s, const void* g) {
    asm volatile("cp.async.cg.shared.global [%0], [%1], 16;" :: "r"(s), "l"(g));
}
__device__ __forceinline__ void cp_commit() { asm volatile("cp.async.commit_group;"); }
template<int NN> __device__ __forceinline__ void cp_wait() {
    asm volatile("cp.async.wait_group %0;" :: "n"(NN));
}
__device__ __forceinline__ void ldsm4(unsigned &r0, unsigned &r1, unsigned &r2, unsigned &r3,
                                      unsigned addr) {
    asm volatile("ldmatrix.sync.aligned.m8n8.x4.shared.b16 {%0,%1,%2,%3}, [%4];"
                 : "=r"(r0), "=r"(r1), "=r"(r2), "=r"(r3) : "r"(addr));
}

// ==========================================================================
// converts
// ==========================================================================
__global__ void convert_h_k(const float* __restrict__ X,
                            __half* __restrict__ Ph, int n4) {
    for (int i = blockIdx.x * blockDim.x + threadIdx.x; i < n4; i += gridDim.x * blockDim.x) {
        float4 v = ((const float4*)X)[i];
        ((__half2*)Ph)[i * 2]     = __floats2half2_rn(v.x, v.y);
        ((__half2*)Ph)[i * 2 + 1] = __floats2half2_rn(v.z, v.w);
    }
}

__global__ void concat_ow_h_k(const float* __restrict__ off_w, const float* __restrict__ off_b,
                              const float* __restrict__ aw_w,  const float* __restrict__ aw_b,
                              __half* __restrict__ Wc, float* __restrict__ Bc) {
    int n = blockIdx.x, l = blockIdx.y, c = threadIdx.x;
    const float* src = (n < 128) ? off_w + (size_t)(l * 128 + n) * HC_
                                 : aw_w  + (size_t)(l * 64 + (n - 128)) * HC_;
    Wc[(size_t)(l * NOA_ + n) * HC_ + c] = __float2half_rn(src[c]);
    if (c == 0)
        Bc[l * NOA_ + n] = (n < 128) ? off_b[l * 128 + n] : aw_b[l * 64 + n - 128];
}

// ==========================================================================
// im2col -> fp16 plane
// ==========================================================================
template<int CIN>
__global__ void im2col_h_k(const float* __restrict__ X,
                           __half* __restrict__ Ph) {
    __shared__ float s[4000];
    int hg = blockIdx.x, ci = blockIdx.y, b = blockIdx.z;
    int tid = threadIdx.x;
    const int K = CIN * 100;
    const float* src = X + ((size_t)(b * CIN + ci) * H_ + hg * P_) * W_;
    for (int i = tid; i < 4000; i += 256) s[i] = src[i];
    __syncthreads();
    size_t rowbase = (size_t)(b * LQ_ + hg * Wg_);
    for (int j = tid; j < 4000; j += 256) {
        int wg = j / 100, idx = j - wg * 100;
        int py = idx / 10, px = idx - py * 10;
        Ph[(rowbase + wg) * K + ci * 100 + idx] = __float2half_rn(s[py * 400 + wg * 10 + px]);
    }
}

// ==========================================================================
// fp16 mma.sync fast GEMM, 128x128x32, 2-stage cp.async
// ==========================================================================
#define FB_BIAS 1u
#define FB_GELU 2u
#define FB_F32  4u
#define FB_HALF 8u
#define HSTG 20480

template<unsigned MODE, int SPLIT>
__global__ void __launch_bounds__(256) gfh_k(
        const __half* __restrict__ A_g, const __half* __restrict__ B_g,
        const float* __restrict__ bias, float* __restrict__ C, __half* __restrict__ Ch,
        int N, int K, int y_off) {
    extern __shared__ char smraw[];
    unsigned sbase = smem_u32(smraw);

    int tid = threadIdx.x, warp = tid >> 5, lane = tid & 31;
    int m0 = (blockIdx.y + y_off) * 128, n0 = blockIdx.x * 128;
    int Kc = K / SPLIT;
    int kstart = (SPLIT > 1) ? blockIdx.z * Kc : 0;
    int nk = Kc / 32;
    int wm = (warp >> 2) * 64, wn = (warp & 3) * 32;
    int gid = lane >> 2, tig = lane & 3;

    float acc[4][4][4];
#pragma unroll
    for (int mi = 0; mi < 4; mi++)
#pragma unroll
        for (int ni = 0; ni < 4; ni++)
#pragma unroll
            for (int q = 0; q < 4; q++) acc[mi][ni][q] = 0.f;

    auto load_tile = [&](int kt, int st) {
        int kb = kstart + kt * 32;
        unsigned sb = sbase + st * HSTG;
#pragma unroll
        for (int j = 0; j < 2; j++) {
            int c = j * 256 + tid;
            int row = c >> 2, q = c & 3;
            unsigned so = row * 80 + q * 16;
            cp16(sb +         so, A_g + (size_t)(m0 + row) * K + kb + q * 8);
            cp16(sb + 10240 + so, B_g + (size_t)(n0 + row) * K + kb + q * 8);
        }
    };

    auto compute = [&](int st) {
        unsigned sb = sbase + st * HSTG;
#pragma unroll
        for (int s = 0; s < 2; s++) {
            unsigned ah[4][4], bh[4][2];
            int arow = wm + (lane & 15);
            unsigned abyte = ((lane >> 4) * 16) + s * 32;
#pragma unroll
            for (int mi = 0; mi < 4; mi++) {
                unsigned ad = sb + (arow + mi * 16) * 80 + abyte;
                ldsm4(ah[mi][0], ah[mi][1], ah[mi][2], ah[mi][3], ad);
            }
            int q = lane >> 3, r = lane & 7;
            int brow = wn + ((q >> 1) << 3) + r;
            unsigned bbyte = (q & 1) * 16 + s * 32;
#pragma unroll
            for (int nj = 0; nj < 2; nj++) {
                unsigned bd = sb + 10240 + (brow + nj * 16) * 80 + bbyte;
                unsigned r0, r1, r2, r3;
                ldsm4(r0, r1, r2, r3, bd);
                bh[nj*2][0] = r0; bh[nj*2][1] = r1; bh[nj*2+1][0] = r2; bh[nj*2+1][1] = r3;
            }
#pragma unroll
            for (int mi = 0; mi < 4; mi++)
#pragma unroll
                for (int ni = 0; ni < 4; ni++)
                    mma_f16(acc[mi][ni], ah[mi][0], ah[mi][1], ah[mi][2], ah[mi][3],
                            bh[ni][0], bh[ni][1]);
        }
    };

    load_tile(0, 0);
    cp_commit();
    for (int kt = 0; kt < nk; kt++) {
        if (kt + 1 < nk) {
            load_tile(kt + 1, (kt + 1) & 1);
            cp_commit();
            cp_wait<1>();
        } else {
            cp_wait<0>();
        }
        __syncthreads();
        compute(kt & 1);
        __syncthreads();
    }

#pragma unroll
    for (int mi = 0; mi < 4; mi++) {
#pragma unroll
        for (int ni = 0; ni < 4; ni++) {
            int m = m0 + wm + mi * 16 + gid;
            int n = n0 + wn + ni * 8 + tig * 2;
            float v0 = acc[mi][ni][0], v1 = acc[mi][ni][1];
            float v2 = acc[mi][ni][2], v3 = acc[mi][ni][3];
            if (SPLIT > 1) {
                float* Cp = C + (size_t)blockIdx.z * ((size_t)MT_ * N);
                Cp[(size_t)m * N + n] = v0;       Cp[(size_t)m * N + n + 1] = v1;
                Cp[(size_t)(m + 8) * N + n] = v2; Cp[(size_t)(m + 8) * N + n + 1] = v3;
            } else {
                if (MODE & FB_BIAS) {
                    float b0 = bias[n], b1 = bias[n + 1];
                    v0 += b0; v1 += b1; v2 += b0; v3 += b1;
                }
                if (MODE & FB_GELU) {
                    v0 = gelu_exact(v0); v1 = gelu_exact(v1);
                    v2 = gelu_exact(v2); v3 = gelu_exact(v3);
                }
                size_t o0 = (size_t)m * N + n, o1 = (size_t)(m + 8) * N + n;
                if (MODE & FB_F32) {
                    C[o0] = v0; C[o0 + 1] = v1; C[o1] = v2; C[o1 + 1] = v3;
                }
                if (MODE & FB_HALF) {
                    Ch[o0] = __float2half(v0); Ch[o0 + 1] = __float2half(v1);
                    Ch[o1] = __float2half(v2); Ch[o1 + 1] = __float2half(v3);
                }
            }
        }
    }
}

// ==========================================================================
// Slow-path fp16 NT GEMM: A fp32 inline->fp16, B pre-fp16. 64x64, 128 thr.
// ==========================================================================
#define SSTR 20
template<int HAS_RES, int WRITE_H>
__global__ __launch_bounds__(128) void mma_gemm_h_k(
        const float* __restrict__ A, const __half* __restrict__ B_g,
        const float* __restrict__ bias, const float* __restrict__ R,
        float* __restrict__ C, __half* __restrict__ Ch, int N, int K) {
    __shared__ unsigned Ah[64*SSTR], Bh[64*SSTR];
    int tid  = threadIdx.x;
    int warp = tid >> 5, lane = tid & 31;
    int gid  = lane >> 2, tig = lane & 3;
    int m0 = blockIdx.y * 64, n0 = blockIdx.x * 64;
    int wm = (warp & 1) * 32, wn = (warp >> 1) * 32;

    int row = tid >> 1, half = tid & 1;
    const float* ap = A + (size_t)(m0 + row) * K + half * 16;
    const __half* bp = B_g + (size_t)(n0 + row) * K + half * 16;

    float4 fa[4];
    uint4 fb[2];
#pragma unroll
    for (int i = 0; i < 4; i++) fa[i] = *(const float4*)(ap + i * 4);
#pragma unroll
    for (int i = 0; i < 2; i++) fb[i] = *(const uint4*)(bp + i * 8);

    float acc[2][4][4];
#pragma unroll
    for (int mi = 0; mi < 2; mi++)
#pragma unroll
        for (int ni = 0; ni < 4; ni++)
#pragma unroll
            for (int q = 0; q < 4; q++) acc[mi][ni][q] = 0.f;

    for (int k0 = 0; k0 < K; k0 += 32) {
        int sb = row * SSTR + half * 8;
#pragma unroll
        for (int i = 0; i < 4; i++) {
            Ah[sb + i*2]     = h2u(__floats2half2_rn(fa[i].x, fa[i].y));
            Ah[sb + i*2 + 1] = h2u(__floats2half2_rn(fa[i].z, fa[i].w));
        }
        Bh[sb + 0] = fb[0].x; Bh[sb + 1] = fb[0].y;
        Bh[sb + 2] = fb[0].z; Bh[sb + 3] = fb[0].w;
        Bh[sb + 4] = fb[1].x; Bh[sb + 5] = fb[1].y;
        Bh[sb + 6] = fb[1].z; Bh[sb + 7] = fb[1].w;
        __syncthreads();
        if (k0 + 32 < K) {
#pragma unroll
            for (int i = 0; i < 4; i++) fa[i] = *(const float4*)(ap + k0 + 32 + i * 4);
#pragma unroll
            for (int i = 0; i < 2; i++) fb[i] = *(const uint4*)(bp + k0 + 32 + i * 8);
        }
#pragma unroll
        for (int s = 0; s < 2; s++) {
            unsigned ah[2][4], bh[4][2];
            int p = s * 8 + tig;
#pragma unroll
            for (int mi = 0; mi < 2; mi++) {
                int r0 = (wm + mi * 16 + gid) * SSTR;
                int r8 = r0 + 8 * SSTR;
                ah[mi][0] = Ah[r0 + p];     ah[mi][1] = Ah[r8 + p];
                ah[mi][2] = Ah[r0 + p + 4]; ah[mi][3] = Ah[r8 + p + 4];
            }
#pragma unroll
            for (int ni = 0; ni < 4; ni++) {
                int nr = (wn + ni * 8 + gid) * SSTR;
                bh[ni][0] = Bh[nr + p]; bh[ni][1] = Bh[nr + p + 4];
            }
#pragma unroll
            for (int mi = 0; mi < 2; mi++)
#pragma unroll
                for (int ni = 0; ni < 4; ni++)
                    mma_f16(acc[mi][ni], ah[mi][0], ah[mi][1], ah[mi][2], ah[mi][3],
                            bh[ni][0], bh[ni][1]);
        }
        __syncthreads();
    }
#pragma unroll
    for (int mi = 0; mi < 2; mi++) {
#pragma unroll
        for (int ni = 0; ni < 4; ni++) {
            int m = m0 + wm + mi * 16 + gid;
            int n = n0 + wn + ni * 8 + tig * 2;
            float b0v = bias[n], b1v = bias[n + 1];
            float v0 = acc[mi][ni][0] + b0v, v1 = acc[mi][ni][1] + b1v;
            float v2 = acc[mi][ni][2] + b0v, v3 = acc[mi][ni][3] + b1v;
            if (HAS_RES) {
                const float* rp = R + (size_t)m * N + n;
                v0 += rp[0]; v1 += rp[1];
                v2 += rp[(size_t)8 * N]; v3 += rp[(size_t)8 * N + 1];
            }
            float* cp = C + (size_t)m * N + n;
            cp[0] = v0; cp[1] = v1;
            cp[(size_t)8 * N] = v2; cp[(size_t)8 * N + 1] = v3;
            if (WRITE_H) {
                __half* hp = Ch + (size_t)m * N + n;
                hp[0] = __float2half_rn(v0); hp[1] = __float2half_rn(v1);
                hp[(size_t)8 * N] = __float2half_rn(v2);
                hp[(size_t)8 * N + 1] = __float2half_rn(v3);
            }
        }
    }
}

// ==========================================================================
// Expand scatter (fp16 temp -> fp32 out, + bev residual), z_off for split
// ==========================================================================
__global__ void expand_scatter_k(const __half* __restrict__ T,
                                 const float* __restrict__ bev,
                                 float* __restrict__ out, int z_off) {
    __shared__ float s[400][17];
    int bcg = blockIdx.x, py = blockIdx.y, bz = blockIdx.z + z_off;
    int b = bz / 20, hg = bz % 20;
    int tid = threadIdx.x;
    int mbase = b * LQ_ + hg * Wg_;
    const __half* tb = T + (size_t)mbase * NEXP_ + py * 2560 + bcg * 16;

#pragma unroll
    for (int it = 0; it < 25; it++) {
        int j = it * 256 + tid;
        int unit = j >> 4, bcl = j & 15;
        int wg = unit / 10, px = unit - wg * 10;
        s[unit][bcl] = __half2float(tb[(size_t)wg * NEXP_ + px * 256 + bcl]);
    }
    __syncthreads();

    int rowbase = hg * P_ + py;
#pragma unroll
    for (int it = 0; it < 25; it++) {
        int j = it * 256 + tid;
        int bcl = j / 400, pix = j - bcl * 400;
        int ch = bcg * 16 + bcl;
        size_t gi = (((size_t)b * BC_ + ch) * H_ + rowbase) * W_ + pix;
        out[gi] = s[pix][bcl] + bev[gi];
    }
}

// ==========================================================================
// LayerNorm family
// ==========================================================================
__device__ __forceinline__ float block_ln_val(float x, const float* __restrict__ g,
                                              const float* __restrict__ bt, int c) {
    __shared__ float red[2][8];
    float s = x, sq = x * x;
#pragma unroll
    for (int o = 16; o > 0; o >>= 1) {
        s  += __shfl_down_sync(0xffffffffu, s, o);
        sq += __shfl_down_sync(0xffffffffu, sq, o);
    }
    int w = c >> 5, lane = c & 31;
    if (lane == 0) { red[0][w] = s; red[1][w] = sq; }
    __syncthreads();
    float ts = 0.f, tq = 0.f;
#pragma unroll
    for (int i = 0; i < 8; i++) { ts += red[0][i]; tq += red[1][i]; }
    float mean = ts * (1.0f / HC_);
    float var  = tq * (1.0f / HC_) - mean * mean;
    float inv  = rsqrtf(var + 1e-5f);
    return (x - mean) * inv * g[c] + bt[c];
}

template<int SPLIT>
__global__ void add_pos_ln_red_k(const float* __restrict__ part,
                                 const float* __restrict__ cb,
                                 const float* __restrict__ pos,
                                 const float* __restrict__ g,
                                 const float* __restrict__ bt,
                                 float* __restrict__ Y) {
    int row = blockIdx.x, c = threadIdx.x;
    float x = 0.f;
#pragma unroll
    for (int z = 0; z < SPLIT; z++) x += part[(size_t)z * MT_ * HC_ + (size_t)row * HC_ + c];
    x += cb[c] + pos[(row % LQ_) * HC_ + c];
    Y[(size_t)row * HC_ + c] = block_ln_val(x, g, bt, c);
}

__global__ void ln2_k(const float* __restrict__ X0, float* __restrict__ Y0,
                      const float* __restrict__ X1, float* __restrict__ Y1,
                      const float* __restrict__ g, const float* __restrict__ bt) {
    int row = blockIdx.x, c = threadIdx.x;
    const float* X = blockIdx.y ? X1 : X0;
    float* Y = blockIdx.y ? Y1 : Y0;
    float x = X[(size_t)row * HC_ + c];
    Y[(size_t)row * HC_ + c] = block_ln_val(x, g, bt, c);
}

__global__ void ln_h_k(const float* __restrict__ X,
                       const float* __restrict__ g,
                       const float* __restrict__ bt,
                       __half* __restrict__ Y) {
    int row = blockIdx.x, c = threadIdx.x;
    float x = X[(size_t)row * HC_ + c];
    Y[(size_t)row * HC_ + c] = __float2half_rn(block_ln_val(x, g, bt, c));
}

// ==========================================================================
// Deformable attention
// ==========================================================================
__global__ void deform_k(const float* __restrict__ val,
                         const float* __restrict__ oa,
                         float* __restrict__ attn) {
    int row  = blockIdx.x;
    int h    = threadIdx.x >> 5;
    int lane = threadIdx.x & 31;
    int b = row / LQ_, l = row % LQ_;
    int hg = l / Wg_, wg = l % Wg_;

    float refx = ((float)wg + 0.5f) / (float)Wg_;
    float refy = ((float)hg + 0.5f) / (float)Hg_;

    const float* oarow = oa + (size_t)row * NOA_;
    float lg[NP_];
    float mx = -1e30f;
#pragma unroll
    for (int p = 0; p < NP_; p++) {
        lg[p] = oarow[128 + h * NP_ + p];
        mx = fmaxf(mx, lg[p]);
    }
    float den = 0.f;
#pragma unroll
    for (int p = 0; p < NP_; p++) { lg[p] = expf(lg[p] - mx); den += lg[p]; }
    float invden = 1.0f / den;

    const float* vb = val + (size_t)b * LQ_ * HC_ + h * DH_ + lane;
    float acc = 0.f;

#pragma unroll
    for (int p = 0; p < NP_; p++) {
        float ox = oarow[(h * NP_ + p) * 2 + 0];
        float oy = oarow[(h * NP_ + p) * 2 + 1];
        float x = (refx + ox * (1.0f / Wg_)) * (float)Wg_ - 0.5f;
        float y = (refy + oy * (1.0f / Hg_)) * (float)Hg_ - 0.5f;
        float xf = floorf(x), yf = floorf(y);
        int x0 = (int)xf, y0 = (int)yf;
        float lx = x - xf, ly = y - yf;
        float wp = lg[p] * invden;

        float w00 = (1.f - lx) * (1.f - ly);
        float w10 = lx * (1.f - ly);
        float w01 = (1.f - lx) * ly;
        float w11 = lx * ly;

        if (x0     >= 0 && x0     < Wg_ && y0     >= 0 && y0     < Hg_)
            acc = fmaf(wp * w00, vb[(size_t)(y0 * Wg_ + x0) * HC_], acc);
        if (x0 + 1 >= 0 && x0 + 1 < Wg_ && y0     >= 0 && y0     < Hg_)
            acc = fmaf(wp * w10, vb[(size_t)(y0 * Wg_ + x0 + 1) * HC_], acc);
        if (x0     >= 0 && x0     < Wg_ && y0 + 1 >= 0 && y0 + 1 < Hg_)
            acc = fmaf(wp * w01, vb[(size_t)((y0 + 1) * Wg_ + x0) * HC_], acc);
        if (x0 + 1 >= 0 && x0 + 1 < Wg_ && y0 + 1 >= 0 && y0 + 1 < Hg_)
            acc = fmaf(wp * w11, vb[(size_t)((y0 + 1) * Wg_ + x0 + 1) * HC_], acc);
    }
    attn[(size_t)row * HC_ + h * DH_ + lane] = acc;
}

// ==========================================================================
// host launch
// ==========================================================================
extern "C" void kernel_launch(void* const* d_in, const int* in_sizes, int n_in,
                              void* d_out, int out_size) {
    const float* bev      = (const float*)d_in[0];
    const float* prior    = (const float*)d_in[1];
    const float* pe_bev_w = (const float*)d_in[2];
    const float* pe_bev_b = (const float*)d_in[3];
    const float* pe_pr_w  = (const float*)d_in[4];
    const float* pe_pr_b  = (const float*)d_in[5];
    const float* pos_bev  = (const float*)d_in[6];
    const float* pos_pr   = (const float*)d_in[7];
    const float* ln_bev_g = (const float*)d_in[8];
    const float* ln_bev_b = (const float*)d_in[9];
    const float* ln_pr_g  = (const float*)d_in[10];
    const float* ln_pr_b  = (const float*)d_in[11];
    const float* n1_g     = (const float*)d_in[12];
    const float* n1_b     = (const float*)d_in[13];
    const float* n2_g     = (const float*)d_in[14];
    const float* n2_b     = (const float*)d_in[15];
    const float* off_w    = (const float*)d_in[16];
    const float* off_b    = (const float*)d_in[17];
    const float* aw_w     = (const float*)d_in[18];
    const float* aw_b     = (const float*)d_in[19];
    const float* vp_w     = (const float*)d_in[20];
    const float* vp_b     = (const float*)d_in[21];
    const float* op_w     = (const float*)d_in[22];
    const float* op_b     = (const float*)d_in[23];
    const float* fc1_w    = (const float*)d_in[24];
    const float* fc1_b    = (const float*)d_in[25];
    const float* fc2_w    = (const float*)d_in[26];
    const float* fc2_b    = (const float*)d_in[27];
    const float* expand_w = (const float*)d_in[28];
    float* out = (float*)d_out;

    float *tgt, *pr, *t, *s, *val, *attn, *oa, *mlp, *part, *part2, *oab;
    __half *exph, *imb, *imp, *wb, *wp, *we, *tg16, *t16;
    __half *fc116, *fc216, *vp16, *op16, *oaw16;
    cudaGetSymbolAddress((void**)&tgt,  g_tgt);
    cudaGetSymbolAddress((void**)&pr,   g_pr);
    cudaGetSymbolAddress((void**)&t,    g_t);
    cudaGetSymbolAddress((void**)&s,    g_s);
    cudaGetSymbolAddress((void**)&val,  g_val);
    cudaGetSymbolAddress((void**)&attn, g_attn);
    cudaGetSymbolAddress((void**)&oa,   g_oa);
    cudaGetSymbolAddress((void**)&mlp,  g_mlp);
    cudaGetSymbolAddress((void**)&part, g_part);
    cudaGetSymbolAddress((void**)&part2,g_part2);
    cudaGetSymbolAddress((void**)&oab,  g_oab);
    cudaGetSymbolAddress((void**)&exph, g_exph);
    cudaGetSymbolAddress((void**)&imb,  g_imb);
    cudaGetSymbolAddress((void**)&imp,  g_imp);
    cudaGetSymbolAddress((void**)&wb,   g_wb);
    cudaGetSymbolAddress((void**)&wp,   g_wp);
    cudaGetSymbolAddress((void**)&we,   g_we);
    cudaGetSymbolAddress((void**)&tg16, g_tg16);
    cudaGetSymbolAddress((void**)&t16,  g_t16);
    cudaGetSymbolAddress((void**)&fc116,g_fc116);
    cudaGetSymbolAddress((void**)&fc216,g_fc216);
    cudaGetSymbolAddress((void**)&vp16, g_vp16);
    cudaGetSymbolAddress((void**)&op16, g_op16);
    cudaGetSymbolAddress((void**)&oaw16,g_oaw16);

    cudaFuncSetAttribute(gfh_k<0u,CSPL_>, cudaFuncAttributeMaxDynamicSharedMemorySize, 2*HSTG);
    cudaFuncSetAttribute(gfh_k<FB_HALF,1>, cudaFuncAttributeMaxDynamicSharedMemorySize, 2*HSTG);
    cudaFuncSetAttribute(gfh_k<FB_BIAS|FB_GELU|FB_F32,1>, cudaFuncAttributeMaxDynamicSharedMemorySize, 2*HSTG);

    static cudaStream_t s1 = nullptr, s2 = nullptr;
    static cudaEvent_t ev[16];
    if (!s1) {
        cudaStreamCreateWithFlags(&s1, cudaStreamNonBlocking);
        cudaStreamCreateWithFlags(&s2, cudaStreamNonBlocking);
        for (int i = 0; i < 16; i++) cudaEventCreateWithFlags(&ev[i], cudaEventDisableTiming);
    }

    // ---- fork ----
    cudaEventRecord(ev[0], 0);
    cudaStreamWaitEvent(s1, ev[0], 0);
    cudaStreamWaitEvent(s2, ev[0], 0);

    // s1: bev patch-embed chain (split-K = 8: 400 blocks, ~90% wave util)
    convert_h_k<<<2048, 256, 0, s1>>>(pe_bev_w, wb, HC_*KBEV_/4);
    im2col_h_k<BC_><<<dim3(Hg_, BC_, B_), 256, 0, s1>>>(bev, imb);
    gfh_k<0u,CSPL_><<<dim3(2, 25, CSPL_), 256, 2*HSTG, s1>>>(imb, wb, nullptr, part, nullptr,
                                                             HC_, KBEV_, 0);
    add_pos_ln_red_k<CSPL_><<<MT_, 256, 0, s1>>>(part, pe_bev_b, pos_bev,
                                                 ln_bev_g, ln_bev_b, tgt);
    cudaEventRecord(ev[1], s1);

    // s2: prior patch-embed chain
    convert_h_k<<<512, 256, 0, s2>>>(pe_pr_w, wp, HC_*KPR_/4);
    im2col_h_k<PC_><<<dim3(Hg_, PC_, B_), 256, 0, s2>>>(prior, imp);
    gfh_k<0u,CSPL_><<<dim3(2, 25, CSPL_), 256, 2*HSTG, s2>>>(imp, wp, nullptr, part2, nullptr,
                                                             HC_, KPR_, 0);
    add_pos_ln_red_k<CSPL_><<<MT_, 256, 0, s2>>>(part2, pe_pr_b, pos_pr,
                                                 ln_pr_g, ln_pr_b, pr);
    cudaEventRecord(ev[2], s2);

    // s0: independent weight prep
    convert_h_k<<<256, 256>>>(fc1_w, fc116, 2*MLPD_*HC_/4);
    convert_h_k<<<256, 256>>>(fc2_w, fc216, 2*HC_*MLPD_/4);
    convert_h_k<<<64, 256>>>(vp_w, vp16, 2*HC_*HC_/4);
    convert_h_k<<<64, 256>>>(op_w, op16, 2*HC_*HC_/4);
    convert_h_k<<<2048, 256>>>(expand_w, we, NEXP_*HC_/4);
    concat_ow_h_k<<<dim3(NOA_, 2), 256>>>(off_w, off_b, aw_w, aw_b, oaw16, oab);

    // join
    cudaStreamWaitEvent(0, ev[1], 0);
    cudaStreamWaitEvent(0, ev[2], 0);

    // ---- decoder layers ----
    for (int l = 0; l < 2; l++) {
        int eb = 4 + l * 4;
        ln2_k<<<dim3(MT_, 2), 256>>>(tgt, t, pr, s, n1_g + l * HC_, n1_b + l * HC_);

        cudaEventRecord(ev[eb], 0);
        cudaStreamWaitEvent(s1, ev[eb], 0);
        mma_gemm_h_k<0,0><<<dim3(4, 50), 128, 0, s1>>>(
            s, vp16 + (size_t)l * HC_ * HC_, vp_b + l * HC_, nullptr, val, nullptr, HC_, HC_);
        cudaEventRecord(ev[eb + 1], s1);
        mma_gemm_h_k<0,0><<<dim3(3, 50), 128>>>(
            t, oaw16 + (size_t)l * NOA_ * HC_, oab + l * NOA_, nullptr, oa, nullptr, NOA_, HC_);
        cudaStreamWaitEvent(0, ev[eb + 1], 0);

        deform_k<<<MT_, 256>>>(val, oa, attn);

        mma_gemm_h_k<1,0><<<dim3(4, 50), 128>>>(
            attn, op16 + (size_t)l * HC_ * HC_, op_b + l * HC_, tgt, tgt, nullptr, HC_, HC_);

        ln_h_k<<<MT_, 256>>>(tgt, n2_g + l * HC_, n2_b + l * HC_, t16);
        gfh_k<FB_BIAS|FB_GELU|FB_F32,1><<<dim3(8, 25), 256, 2*HSTG>>>(
            t16, fc116 + (size_t)l * MLPD_ * HC_, fc1_b + l * MLPD_,
            mlp, nullptr, MLPD_, HC_, 0);
        if (l == 1) {
            mma_gemm_h_k<1,1><<<dim3(4, 50), 128>>>(
                mlp, fc216 + (size_t)l * HC_ * MLPD_, fc2_b + l * HC_, tgt, tgt, tg16, HC_, MLPD_);
        } else {
            mma_gemm_h_k<1,0><<<dim3(4, 50), 128>>>(
                mlp, fc216 + (size_t)l * HC_ * MLPD_, fc2_b + l * HC_, tgt, tgt, nullptr, HC_, MLPD_);
        }
    }

    // ---- expand: fp16 GEMM halves pipelined with scatter halves ----
    gfh_k<FB_HALF,1><<<dim3(NEXP_/128, 13), 256, 2*HSTG>>>(
        tg16, we, nullptr, nullptr, exph, NEXP_, HC_, 0);
    cudaEventRecord(ev[12], 0);
    gfh_k<FB_HALF,1><<<dim3(NEXP_/128, 12), 256, 2*HSTG>>>(
        tg16, we, nullptr, nullptr, exph, NEXP_, HC_, 13);
    cudaStreamWaitEvent(s1, ev[12], 0);
    expand_scatter_k<<<dim3(16, 10, 41), 256, 0, s1>>>(exph, bev, out, 0);
    cudaEventRecord(ev[13], s1);
    expand_scatter_k<<<dim3(16, 10, 39), 256>>>(exph, bev, out, 41);
    cudaStreamWaitEvent(0, ev[13], 0);
}